// round 1
// baseline (speedup 1.0000x reference)
#include <cuda_runtime.h>
#include <cuda_bf16.h>
#include <cstdint>

// Problem constants
#define BB 2
#define CC 256
#define HH 96
#define WW 96
#define HWP (HH*WW)          // 9216
#define K9 9
#define EPSBN 1e-5f

// ---------------- scratch (device globals; no dynamic allocation) -------------
__device__ float g_om[BB * 27 * HWP];                   // offset conv output
__device__ int4  g_sidx[BB * K9 * HWP];                 // 4 corner pixel indices
__device__ float4 g_sw[BB * K9 * HWP];                  // 4 bilinear weights * mask
__device__ float g_W2[K9 * CC * CC];                    // w_conv repacked [k][c][o]
__device__ float g_Z[(size_t)BB * K9 * HWP * CC];       // Z_k = W_k^T X, [bk][p][o]  (~170MB)

// =============================================================================
// K1: offset conv  om[b][27][h][w] = conv3x3(x, w_off) + b_off
// block: 256 thr = 64 pixels (8x8 tile) x 4 channel-groups of 64 channels
// =============================================================================
__global__ __launch_bounds__(256) void offset_conv_kernel(
    const float* __restrict__ x, const float* __restrict__ w_off,
    const float* __restrict__ b_off)
{
    __shared__ float patch[4][100];      // 10x10 halo patch per group
    __shared__ float wsm[4][27 * 12];    // 27 outputs x 9 taps, stride 12 (align)
    __shared__ float red[256];

    const int b    = blockIdx.y;
    const int tile = blockIdx.x;               // 0..143
    const int ty0  = (tile / 12) * 8;
    const int tx0  = (tile % 12) * 8;
    const int tid  = threadIdx.x;
    const int grp  = tid >> 6;                 // 0..3
    const int lid  = tid & 63;                 // 0..63
    const int pr   = lid >> 3, pc = lid & 7;   // pixel in tile

    float acc[27];
#pragma unroll
    for (int o = 0; o < 27; o++) acc[o] = 0.f;

    const float* xb = x + (size_t)b * CC * HWP;

    for (int ci = 0; ci < 64; ci++) {
        const int c = grp * 64 + ci;
        const float* xc = xb + (size_t)c * HWP;
        // load 10x10 patch (zero pad)
        for (int i = lid; i < 100; i += 64) {
            const int py = ty0 - 1 + i / 10;
            const int px = tx0 - 1 + i % 10;
            float v = 0.f;
            if (py >= 0 && py < HH && px >= 0 && px < WW) v = xc[py * WW + px];
            patch[grp][i] = v;
        }
        // load 27x9 weights for channel c
        const float* wc = w_off + c * 9;
        for (int j = lid; j < 243; j += 64) {
            const int o = j / 9, kk = j - o * 9;
            wsm[grp][o * 12 + kk] = wc[o * 2304 + kk];
        }
        __syncthreads();

        float pv[9];
#pragma unroll
        for (int yy = 0; yy < 3; yy++)
#pragma unroll
            for (int xx = 0; xx < 3; xx++)
                pv[yy * 3 + xx] = patch[grp][(pr + yy) * 10 + (pc + xx)];

#pragma unroll
        for (int o = 0; o < 27; o++) {
#pragma unroll
            for (int kk = 0; kk < 9; kk++)
                acc[o] += pv[kk] * wsm[grp][o * 12 + kk];
        }
        __syncthreads();
    }

    const int pix = (ty0 + pr) * WW + (tx0 + pc);
    for (int o = 0; o < 27; o++) {
        red[tid] = acc[o];
        __syncthreads();
        if (grp == 0) {
            const float s = red[lid] + red[64 + lid] + red[128 + lid] + red[192 + lid]
                          + b_off[o];
            g_om[((size_t)b * 27 + o) * HWP + pix] = s;
        }
        __syncthreads();
    }
}

// =============================================================================
// K2: per (b,k,p): sigmoid mask, corner indices + weights (mask folded in)
// =============================================================================
__global__ void prep_kernel()
{
    const int t = blockIdx.x * blockDim.x + threadIdx.x;
    if (t >= BB * K9 * HWP) return;
    const int p  = t % HWP;
    const int bk = t / HWP;
    const int k  = bk % K9;
    const int b  = bk / K9;

    const float* omb = g_om + (size_t)b * 27 * HWP;
    const float dy = omb[(2 * k) * HWP + p];
    const float dx = omb[(2 * k + 1) * HWP + p];
    const float mv = omb[(18 + k) * HWP + p];
    const float m  = 1.f / (1.f + expf(-mv));

    const int h = p / WW, w = p - h * WW;
    const float py = (float)h + (float)(k / 3 - 1) + dy;
    const float px = (float)w + (float)(k % 3 - 1) + dx;
    const float y0f = floorf(py), x0f = floorf(px);
    const float ly = py - y0f, lx = px - x0f;
    const int y0 = (int)y0f, x0 = (int)x0f;
    const int y1 = y0 + 1,   x1 = x0 + 1;

    const bool vy0 = (y0 >= 0) & (y0 < HH);
    const bool vy1 = (y1 >= 0) & (y1 < HH);
    const bool vx0 = (x0 >= 0) & (x0 < WW);
    const bool vx1 = (x1 >= 0) & (x1 < WW);
    const int y0c = min(max(y0, 0), HH - 1), y1c = min(max(y1, 0), HH - 1);
    const int x0c = min(max(x0, 0), WW - 1), x1c = min(max(x1, 0), WW - 1);

    int4 idx;
    idx.x = y0c * WW + x0c;
    idx.y = y0c * WW + x1c;
    idx.z = y1c * WW + x0c;
    idx.w = y1c * WW + x1c;
    float4 wt;
    wt.x = (1.f - ly) * (1.f - lx) * m * ((vy0 & vx0) ? 1.f : 0.f);
    wt.y = (1.f - ly) * lx         * m * ((vy0 & vx1) ? 1.f : 0.f);
    wt.z = ly * (1.f - lx)         * m * ((vy1 & vx0) ? 1.f : 0.f);
    wt.w = ly * lx                 * m * ((vy1 & vx1) ? 1.f : 0.f);

    g_sidx[t] = idx;
    g_sw[t]   = wt;
}

// =============================================================================
// K2b: repack w_conv [o][c][3][3] -> g_W2[k][c][o]
// =============================================================================
__global__ void pack_w2_kernel(const float* __restrict__ w_conv)
{
    const int t = blockIdx.x * blockDim.x + threadIdx.x;
    if (t >= K9 * CC * CC) return;
    const int k = t / (CC * CC);
    const int r = t % (CC * CC);
    const int c = r / CC;
    const int o = r % CC;
    g_W2[t] = w_conv[(o * CC + c) * 9 + k];
}

// =============================================================================
// K3: Z[bk][p][o] = sum_c x[b][c][p] * W2[k][c][o]
// M=9216(p), N=256(o), K=256(c). BM=128 BN=128 BK=16, 256 thr, 8x8/thread.
// =============================================================================
#define GBM 128
#define GBN 128
#define GBK 16
__global__ __launch_bounds__(256) void gemm_z_kernel(const float* __restrict__ x)
{
    const int z = blockIdx.z;               // 0..17
    const int b = z / K9;
    const float* A  = x + (size_t)b * CC * HWP;       // [c][p]
    const float* Bw = g_W2 + (size_t)(z % K9) * CC * CC;  // [c][o]
    float* Cc = g_Z + (size_t)z * HWP * CC;           // [p][o]

    const int m0 = blockIdx.x * GBM;
    const int n0 = blockIdx.y * GBN;

    __shared__ float As[2][GBK][GBM];
    __shared__ float Bs[2][GBK][GBN];

    const int tid = threadIdx.x;
    const int ar = tid >> 5;        // 0..7
    const int ac = tid & 31;        // 0..31
    const int ty = tid >> 4;        // 0..15  (p sub-tile)
    const int tx = tid & 15;        // 0..15  (o sub-tile)

    float acc[8][8];
#pragma unroll
    for (int i = 0; i < 8; i++)
#pragma unroll
        for (int j = 0; j < 8; j++) acc[i][j] = 0.f;

    // prologue: tile 0
    {
        *(float4*)&As[0][ar][ac * 4]     = *(const float4*)&A[(size_t)ar * HWP + m0 + ac * 4];
        *(float4*)&As[0][ar + 8][ac * 4] = *(const float4*)&A[(size_t)(ar + 8) * HWP + m0 + ac * 4];
        *(float4*)&Bs[0][ar][ac * 4]     = *(const float4*)&Bw[(size_t)ar * CC + n0 + ac * 4];
        *(float4*)&Bs[0][ar + 8][ac * 4] = *(const float4*)&Bw[(size_t)(ar + 8) * CC + n0 + ac * 4];
    }
    __syncthreads();

    for (int kt = 0; kt < CC / GBK; kt++) {
        const int cur = kt & 1;
        float4 pa0, pa1, pb0, pb1;
        if (kt < CC / GBK - 1) {
            const int c0 = (kt + 1) * GBK;
            pa0 = *(const float4*)&A[(size_t)(c0 + ar) * HWP + m0 + ac * 4];
            pa1 = *(const float4*)&A[(size_t)(c0 + ar + 8) * HWP + m0 + ac * 4];
            pb0 = *(const float4*)&Bw[(size_t)(c0 + ar) * CC + n0 + ac * 4];
            pb1 = *(const float4*)&Bw[(size_t)(c0 + ar + 8) * CC + n0 + ac * 4];
        }
#pragma unroll
        for (int c = 0; c < GBK; c++) {
            float ra[8], rb[8];
            *(float4*)&ra[0] = *(const float4*)&As[cur][c][ty * 8];
            *(float4*)&ra[4] = *(const float4*)&As[cur][c][ty * 8 + 4];
            *(float4*)&rb[0] = *(const float4*)&Bs[cur][c][tx * 8];
            *(float4*)&rb[4] = *(const float4*)&Bs[cur][c][tx * 8 + 4];
#pragma unroll
            for (int i = 0; i < 8; i++)
#pragma unroll
                for (int j = 0; j < 8; j++)
                    acc[i][j] += ra[i] * rb[j];
        }
        if (kt < CC / GBK - 1) {
            const int nxt = cur ^ 1;
            *(float4*)&As[nxt][ar][ac * 4]     = pa0;
            *(float4*)&As[nxt][ar + 8][ac * 4] = pa1;
            *(float4*)&Bs[nxt][ar][ac * 4]     = pb0;
            *(float4*)&Bs[nxt][ar + 8][ac * 4] = pb1;
        }
        __syncthreads();
    }

#pragma unroll
    for (int i = 0; i < 8; i++) {
        float* crow = Cc + (size_t)(m0 + ty * 8 + i) * CC + n0 + tx * 8;
        *(float4*)&crow[0] = *(float4*)&acc[i][0];
        *(float4*)&crow[4] = *(float4*)&acc[i][4];
    }
}

// =============================================================================
// K4: combine: y[o,p] = sum_{k,j} w[k,j,p] * Z[bk][idx][o]; BN+ReLU+residual
// block: 256 thr = 32 pixels x 8 o-groups (32 o each, float4-interleaved)
// =============================================================================
__global__ __launch_bounds__(256) void combine_kernel(
    const float* __restrict__ x, const float* __restrict__ b_conv,
    const float* __restrict__ gamma, const float* __restrict__ beta,
    const float* __restrict__ run_mean, const float* __restrict__ run_var,
    float* __restrict__ out)
{
    __shared__ int   sI[32][36];
    __shared__ float sWt[32][36];
    __shared__ float sA[256], sB[256];
    __shared__ float trans[256 * 33];

    const int b  = blockIdx.y;
    const int p0 = blockIdx.x * 32;
    const int tid = threadIdx.x;

    // BN params: val' = y*sA[o] + sB[o]
    {
        const int o = tid;
        const float inv = rsqrtf(run_var[o] + EPSBN);
        const float a = inv * gamma[o];
        sA[o] = a;
        sB[o] = (b_conv[o] - run_mean[o]) * a + beta[o];
    }
    // stage sampling metadata: 32 px * 9 k
    for (int i = tid; i < 32 * 9; i += 256) {
        const int px = i % 32;
        const int k  = i / 32;
        const size_t t = ((size_t)(b * K9 + k)) * HWP + p0 + px;
        *(int4*)&sI[px][k * 4]    = g_sidx[t];
        *(float4*)&sWt[px][k * 4] = g_sw[t];
    }
    __syncthreads();

    const int og  = tid & 7;    // o-group
    const int pxl = tid >> 3;   // 0..31

    float acc[8][4];
#pragma unroll
    for (int t = 0; t < 8; t++)
#pragma unroll
        for (int e = 0; e < 4; e++) acc[t][e] = 0.f;

    for (int k = 0; k < K9; k++) {
        const float4* Zk4 = reinterpret_cast<const float4*>(
            g_Z + ((size_t)(b * K9 + k)) * HWP * CC);
#pragma unroll
        for (int j = 0; j < 4; j++) {
            const int   idx = sI[pxl][k * 4 + j];
            const float wj  = sWt[pxl][k * 4 + j];
            const float4* src = Zk4 + (size_t)idx * 64 + og;
#pragma unroll
            for (int t = 0; t < 8; t++) {
                const float4 v = src[t * 8];   // float offset og*4 + 32*t
                acc[t][0] += wj * v.x;
                acc[t][1] += wj * v.y;
                acc[t][2] += wj * v.z;
                acc[t][3] += wj * v.w;
            }
        }
    }

    // transpose via smem (padded stride 33 -> conflict free)
#pragma unroll
    for (int t = 0; t < 8; t++)
#pragma unroll
        for (int e = 0; e < 4; e++) {
            const int o = og * 4 + t * 32 + e;
            trans[o * 33 + pxl] = acc[t][e];
        }
    __syncthreads();

    const float* xb = x + ((size_t)b * CC) * HWP;
    float* ob = out + ((size_t)b * CC) * HWP;
    for (int pass = 0; pass < 32; pass++) {
        const int o   = (tid >> 5) + pass * 8;
        const int pxi = tid & 31;
        float v = trans[o * 33 + pxi];
        v = fmaxf(v * sA[o] + sB[o], 0.f);
        const size_t gi = (size_t)o * HWP + p0 + pxi;
        ob[gi] = xb[gi] + v;
    }
}

// =============================================================================
extern "C" void kernel_launch(void* const* d_in, const int* in_sizes, int n_in,
                              void* d_out, int out_size)
{
    const float* x        = (const float*)d_in[0];
    const float* w_off    = (const float*)d_in[1];
    const float* b_off    = (const float*)d_in[2];
    const float* w_conv   = (const float*)d_in[3];
    const float* b_conv   = (const float*)d_in[4];
    const float* gamma    = (const float*)d_in[5];
    const float* beta     = (const float*)d_in[6];
    const float* run_mean = (const float*)d_in[7];
    const float* run_var  = (const float*)d_in[8];
    float* out = (float*)d_out;

    offset_conv_kernel<<<dim3(144, BB), 256>>>(x, w_off, b_off);
    prep_kernel<<<(BB * K9 * HWP + 255) / 256, 256>>>();
    pack_w2_kernel<<<(K9 * CC * CC + 255) / 256, 256>>>(w_conv);
    gemm_z_kernel<<<dim3(HWP / GBM, CC / GBN, BB * K9), 256>>>(x);
    combine_kernel<<<dim3(HWP / 32, BB), 256>>>(x, b_conv, gamma, beta,
                                                run_mean, run_var, out);
}

// round 3
// speedup vs baseline: 1.7844x; 1.7844x over previous
#include <cuda_runtime.h>
#include <cuda_bf16.h>
#include <cstdint>

// Problem constants
#define BB 2
#define CC 256
#define HH 96
#define WW 96
#define HWP (HH*WW)          // 9216
#define K9 9
#define EPSBN 1e-5f

// ---------------- scratch (device globals; no dynamic allocation) -------------
__device__ float  g_om[BB * 27 * HWP];                  // offset conv output
__device__ int4   g_sidx[BB * K9 * HWP];                // 4 corner pixel indices
__device__ float4 g_sw[BB * K9 * HWP];                  // 4 bilinear weights * mask
__device__ float  g_Z[(size_t)BB * K9 * HWP * CC];      // Z_k = W_k^T X, [bk][p][o]
__device__ float  g_A[(size_t)BB * HWP * CC];           // tf32 [b][p][c]
__device__ float  g_Bw[(size_t)K9 * CC * CC];           // tf32 [k][o][c]

// ---------------- helpers ------------------------------------------------------
__device__ __forceinline__ uint32_t smem_u32(const void* p) {
    uint32_t a;
    asm("{ .reg .u64 t; cvta.to.shared.u64 t, %1; cvt.u32.u64 %0, t; }"
        : "=r"(a) : "l"(p));
    return a;
}
__device__ __forceinline__ float to_tf32(float x) {
    float y;
    asm("cvt.rna.tf32.f32 %0, %1;" : "=f"(y) : "f"(x));
    return y;
}
__device__ __forceinline__ void cp_async16(uint32_t s, const void* g) {
    asm volatile("cp.async.cg.shared.global [%0], [%1], 16;" :: "r"(s), "l"(g));
}
#define CP_COMMIT() asm volatile("cp.async.commit_group;" ::: "memory")
#define CP_WAIT0()  asm volatile("cp.async.wait_group 0;" ::: "memory")

__device__ __forceinline__ void mma_tf32(float* d, const uint32_t* a, const uint32_t* b) {
    asm volatile(
        "mma.sync.aligned.m16n8k8.row.col.f32.tf32.tf32.f32 "
        "{%0,%1,%2,%3}, {%4,%5,%6,%7}, {%8,%9}, {%0,%1,%2,%3};"
        : "+f"(d[0]), "+f"(d[1]), "+f"(d[2]), "+f"(d[3])
        : "r"(a[0]), "r"(a[1]), "r"(a[2]), "r"(a[3]), "r"(b[0]), "r"(b[1]));
}

// =============================================================================
// K1: offset conv  om[b][27][h][w] = conv3x3(x, w_off) + b_off
// =============================================================================
__global__ __launch_bounds__(256) void offset_conv_kernel(
    const float* __restrict__ x, const float* __restrict__ w_off,
    const float* __restrict__ b_off)
{
    __shared__ float patch[4][100];
    __shared__ float wsm[4][27 * 12];
    __shared__ float red[256];

    const int b    = blockIdx.y;
    const int tile = blockIdx.x;
    const int ty0  = (tile / 12) * 8;
    const int tx0  = (tile % 12) * 8;
    const int tid  = threadIdx.x;
    const int grp  = tid >> 6;
    const int lid  = tid & 63;
    const int pr   = lid >> 3, pc = lid & 7;

    float acc[27];
#pragma unroll
    for (int o = 0; o < 27; o++) acc[o] = 0.f;

    const float* xb = x + (size_t)b * CC * HWP;

    for (int ci = 0; ci < 64; ci++) {
        const int c = grp * 64 + ci;
        const float* xc = xb + (size_t)c * HWP;
        for (int i = lid; i < 100; i += 64) {
            const int py = ty0 - 1 + i / 10;
            const int px = tx0 - 1 + i % 10;
            float v = 0.f;
            if (py >= 0 && py < HH && px >= 0 && px < WW) v = xc[py * WW + px];
            patch[grp][i] = v;
        }
        const float* wc = w_off + c * 9;
        for (int j = lid; j < 243; j += 64) {
            const int o = j / 9, kk = j - o * 9;
            wsm[grp][o * 12 + kk] = wc[o * 2304 + kk];
        }
        __syncthreads();

        float pv[9];
#pragma unroll
        for (int yy = 0; yy < 3; yy++)
#pragma unroll
            for (int xx = 0; xx < 3; xx++)
                pv[yy * 3 + xx] = patch[grp][(pr + yy) * 10 + (pc + xx)];

#pragma unroll
        for (int o = 0; o < 27; o++) {
#pragma unroll
            for (int kk = 0; kk < 9; kk++)
                acc[o] += pv[kk] * wsm[grp][o * 12 + kk];
        }
        __syncthreads();
    }

    const int pix = (ty0 + pr) * WW + (tx0 + pc);
    for (int o = 0; o < 27; o++) {
        red[tid] = acc[o];
        __syncthreads();
        if (grp == 0) {
            const float s = red[lid] + red[64 + lid] + red[128 + lid] + red[192 + lid]
                          + b_off[o];
            g_om[((size_t)b * 27 + o) * HWP + pix] = s;
        }
        __syncthreads();
    }
}

// =============================================================================
// K2: per (b,k,p): sigmoid mask, corner indices + weights (mask folded in)
// =============================================================================
__global__ void prep_kernel()
{
    const int t = blockIdx.x * blockDim.x + threadIdx.x;
    if (t >= BB * K9 * HWP) return;
    const int p  = t % HWP;
    const int bk = t / HWP;
    const int k  = bk % K9;
    const int b  = bk / K9;

    const float* omb = g_om + (size_t)b * 27 * HWP;
    const float dy = omb[(2 * k) * HWP + p];
    const float dx = omb[(2 * k + 1) * HWP + p];
    const float mv = omb[(18 + k) * HWP + p];
    const float m  = 1.f / (1.f + expf(-mv));

    const int h = p / WW, w = p - h * WW;
    const float py = (float)h + (float)(k / 3 - 1) + dy;
    const float px = (float)w + (float)(k % 3 - 1) + dx;
    const float y0f = floorf(py), x0f = floorf(px);
    const float ly = py - y0f, lx = px - x0f;
    const int y0 = (int)y0f, x0 = (int)x0f;
    const int y1 = y0 + 1,   x1 = x0 + 1;

    const bool vy0 = (y0 >= 0) & (y0 < HH);
    const bool vy1 = (y1 >= 0) & (y1 < HH);
    const bool vx0 = (x0 >= 0) & (x0 < WW);
    const bool vx1 = (x1 >= 0) & (x1 < WW);
    const int y0c = min(max(y0, 0), HH - 1), y1c = min(max(y1, 0), HH - 1);
    const int x0c = min(max(x0, 0), WW - 1), x1c = min(max(x1, 0), WW - 1);

    int4 idx;
    idx.x = y0c * WW + x0c;
    idx.y = y0c * WW + x1c;
    idx.z = y1c * WW + x0c;
    idx.w = y1c * WW + x1c;
    float4 wt;
    wt.x = (1.f - ly) * (1.f - lx) * m * ((vy0 & vx0) ? 1.f : 0.f);
    wt.y = (1.f - ly) * lx         * m * ((vy0 & vx1) ? 1.f : 0.f);
    wt.z = ly * (1.f - lx)         * m * ((vy1 & vx0) ? 1.f : 0.f);
    wt.w = ly * lx                 * m * ((vy1 & vx1) ? 1.f : 0.f);

    g_sidx[t] = idx;
    g_sw[t]   = wt;
}

// =============================================================================
// K2b: transpose + tf32 round: x[b][c][p] -> g_A[b][p][c]
// =============================================================================
__global__ __launch_bounds__(256) void pack_a_kernel(const float* __restrict__ x)
{
    __shared__ float t[32][33];
    const int b  = blockIdx.z;
    const int p0 = blockIdx.x * 32;
    const int c0 = blockIdx.y * 32;
    const int tx = threadIdx.x, ty = threadIdx.y;   // (32, 8)

    const float* xb = x + ((size_t)b * CC + c0) * HWP + p0;
#pragma unroll
    for (int i = 0; i < 32; i += 8)
        t[ty + i][tx] = xb[(size_t)(ty + i) * HWP + tx];
    __syncthreads();

    float* A = g_A + ((size_t)b * HWP + p0) * CC + c0;
#pragma unroll
    for (int i = 0; i < 32; i += 8)
        A[(size_t)(ty + i) * CC + tx] = to_tf32(t[tx][ty + i]);
}

// =============================================================================
// K2c: repack + tf32 round: w_conv [o][c][3][3] -> g_Bw[k][o][c]
// =============================================================================
__global__ void pack_w_kernel(const float* __restrict__ w_conv)
{
    const int t = blockIdx.x * blockDim.x + threadIdx.x;
    if (t >= K9 * CC * CC) return;
    const int k = t / (CC * CC);
    const int r = t % (CC * CC);
    const int o = r / CC;
    const int c = r % CC;
    g_Bw[t] = to_tf32(w_conv[((size_t)o * CC + c) * 9 + k]);
}

// =============================================================================
// K3: TF32 mma.sync GEMM.  Z[z][p][o] = sum_c A[b][p][c] * B[k][o][c]
// BM=128, BN=128, BK=32, 128 thr = 4 warps (2x2), warp tile 64x64, m16n8k8
// =============================================================================
#define BK 32
#define APAD 4
#define AROWF (BK + APAD)                 // 36 floats per smem row
#define STAGEF (128 * AROWF)              // floats per (A or B) stage
#define GEMM_SMEM (4 * STAGEF * 4)        // 2 bufs x (A+B) = 73728 bytes

__global__ __launch_bounds__(128, 2) void gemm_tf32_kernel()
{
    extern __shared__ __align__(16) float dsm[];
    float* Asm = dsm;                    // [2][128][36]
    float* Bsm = dsm + 2 * STAGEF;       // [2][128][36]
    const uint32_t sA0 = smem_u32(Asm);
    const uint32_t sB0 = smem_u32(Bsm);

    const int tid  = threadIdx.x;
    const int warp = tid >> 5;
    const int lane = tid & 31;
    const int gid  = lane >> 2;          // 0..7
    const int qid  = lane & 3;           // 0..3
    const int wy   = warp >> 1;          // 0..1 (m)
    const int wx   = warp & 1;           // 0..1 (n)

    const int p0 = blockIdx.x * 128;
    const int n0 = blockIdx.y * 128;
    const int z  = blockIdx.z;           // b*9 + k
    const int b  = z / K9, k = z % K9;

    const float* Ag = g_A  + ((size_t)b * HWP + p0) * CC;    // row stride CC
    const float* Bg = g_Bw + ((size_t)k * CC + n0) * CC;     // row stride CC

    // per-thread load slots: idx = it*128 + tid; row = idx>>3, j = idx&7
    const int lrow = tid >> 3;           // base row (advances by 16 per it)
    const int lj   = tid & 7;            // float4 index within 32-float row

    auto load_stage = [&](int s, int kc) {
        const int c0 = kc * BK + lj * 4;
        const uint32_t sa = sA0 + (uint32_t)(s * STAGEF) * 4;
        const uint32_t sb = sB0 + (uint32_t)(s * STAGEF) * 4;
#pragma unroll
        for (int it = 0; it < 8; it++) {
            const int row = lrow + it * 16;
            cp_async16(sa + (uint32_t)(row * AROWF + lj * 4) * 4,
                       Ag + (size_t)row * CC + c0);
            cp_async16(sb + (uint32_t)(row * AROWF + lj * 4) * 4,
                       Bg + (size_t)row * CC + c0);
        }
        CP_COMMIT();
    };

    float acc[4][8][4];
#pragma unroll
    for (int mt = 0; mt < 4; mt++)
#pragma unroll
        for (int nt = 0; nt < 8; nt++)
#pragma unroll
            for (int e = 0; e < 4; e++) acc[mt][nt][e] = 0.f;

    load_stage(0, 0);
    CP_WAIT0();
    __syncthreads();

#pragma unroll 1
    for (int kc = 0; kc < CC / BK; kc++) {
        const int cur = kc & 1;
        if (kc < CC / BK - 1) load_stage(cur ^ 1, kc + 1);

        const float* Af = Asm + cur * STAGEF + (wy * 64 + gid) * AROWF;
        const float* Bf = Bsm + cur * STAGEF + (wx * 64 + gid) * AROWF;

#pragma unroll
        for (int ks = 0; ks < 4; ks++) {
            const int c = ks * 8 + qid;
            uint32_t afr[4][4], bfr[8][2];
#pragma unroll
            for (int mt = 0; mt < 4; mt++) {
                const float* ap = Af + mt * 16 * AROWF;
                afr[mt][0] = __float_as_uint(ap[c]);
                afr[mt][1] = __float_as_uint(ap[8 * AROWF + c]);
                afr[mt][2] = __float_as_uint(ap[c + 4]);
                afr[mt][3] = __float_as_uint(ap[8 * AROWF + c + 4]);
            }
#pragma unroll
            for (int nt = 0; nt < 8; nt++) {
                const float* bp = Bf + nt * 8 * AROWF;
                bfr[nt][0] = __float_as_uint(bp[c]);
                bfr[nt][1] = __float_as_uint(bp[c + 4]);
            }
#pragma unroll
            for (int mt = 0; mt < 4; mt++)
#pragma unroll
                for (int nt = 0; nt < 8; nt++)
                    mma_tf32(acc[mt][nt], afr[mt], bfr[nt]);
        }
        if (kc < CC / BK - 1) CP_WAIT0();
        __syncthreads();
    }

    // epilogue: D tile -> g_Z[z][p][o]
    float* Zb = g_Z + ((size_t)z * HWP) * CC;
#pragma unroll
    for (int mt = 0; mt < 4; mt++) {
        const int row = p0 + wy * 64 + mt * 16 + gid;
        float* z0 = Zb + (size_t)row * CC + n0 + wx * 64 + qid * 2;
        float* z1 = z0 + 8 * CC;
#pragma unroll
        for (int nt = 0; nt < 8; nt++) {
            *(float2*)(z0 + nt * 8) = make_float2(acc[mt][nt][0], acc[mt][nt][1]);
            *(float2*)(z1 + nt * 8) = make_float2(acc[mt][nt][2], acc[mt][nt][3]);
        }
    }
}

// =============================================================================
// K4: combine: y[o,p] = sum_{k,j} w[k,j,p] * Z[bk][idx][o]; BN+ReLU+residual
// =============================================================================
__global__ __launch_bounds__(256) void combine_kernel(
    const float* __restrict__ x, const float* __restrict__ b_conv,
    const float* __restrict__ gamma, const float* __restrict__ beta,
    const float* __restrict__ run_mean, const float* __restrict__ run_var,
    float* __restrict__ out)
{
    __shared__ int   sI[32][36];
    __shared__ float sWt[32][36];
    __shared__ float sA[256], sB[256];
    __shared__ float trans[256 * 33];

    const int b  = blockIdx.y;
    const int p0 = blockIdx.x * 32;
    const int tid = threadIdx.x;

    {
        const int o = tid;
        const float inv = rsqrtf(run_var[o] + EPSBN);
        const float a = inv * gamma[o];
        sA[o] = a;
        sB[o] = (b_conv[o] - run_mean[o]) * a + beta[o];
    }
    for (int i = tid; i < 32 * 9; i += 256) {
        const int px = i % 32;
        const int k  = i / 32;
        const size_t t = ((size_t)(b * K9 + k)) * HWP + p0 + px;
        *(int4*)&sI[px][k * 4]    = g_sidx[t];
        *(float4*)&sWt[px][k * 4] = g_sw[t];
    }
    __syncthreads();

    const int og  = tid & 7;
    const int pxl = tid >> 3;

    float acc[8][4];
#pragma unroll
    for (int t = 0; t < 8; t++)
#pragma unroll
        for (int e = 0; e < 4; e++) acc[t][e] = 0.f;

    for (int k = 0; k < K9; k++) {
        const float4* Zk4 = reinterpret_cast<const float4*>(
            g_Z + ((size_t)(b * K9 + k)) * HWP * CC);
#pragma unroll
        for (int j = 0; j < 4; j++) {
            const int   idx = sI[pxl][k * 4 + j];
            const float wj  = sWt[pxl][k * 4 + j];
            const float4* src = Zk4 + (size_t)idx * 64 + og;
#pragma unroll
            for (int t = 0; t < 8; t++) {
                const float4 v = src[t * 8];
                acc[t][0] += wj * v.x;
                acc[t][1] += wj * v.y;
                acc[t][2] += wj * v.z;
                acc[t][3] += wj * v.w;
            }
        }
    }

#pragma unroll
    for (int t = 0; t < 8; t++)
#pragma unroll
        for (int e = 0; e < 4; e++) {
            const int o = og * 4 + t * 32 + e;
            trans[o * 33 + pxl] = acc[t][e];
        }
    __syncthreads();

    const float* xb = x + ((size_t)b * CC) * HWP;
    float* ob = out + ((size_t)b * CC) * HWP;
    for (int pass = 0; pass < 32; pass++) {
        const int o   = (tid >> 5) + pass * 8;
        const int pxi = tid & 31;
        float v = trans[o * 33 + pxi];
        v = fmaxf(v * sA[o] + sB[o], 0.f);
        const size_t gi = (size_t)o * HWP + p0 + pxi;
        ob[gi] = xb[gi] + v;
    }
}

// =============================================================================
extern "C" void kernel_launch(void* const* d_in, const int* in_sizes, int n_in,
                              void* d_out, int out_size)
{
    const float* x        = (const float*)d_in[0];
    const float* w_off    = (const float*)d_in[1];
    const float* b_off    = (const float*)d_in[2];
    const float* w_conv   = (const float*)d_in[3];
    const float* b_conv   = (const float*)d_in[4];
    const float* gamma    = (const float*)d_in[5];
    const float* beta     = (const float*)d_in[6];
    const float* run_mean = (const float*)d_in[7];
    const float* run_var  = (const float*)d_in[8];
    float* out = (float*)d_out;

    cudaFuncSetAttribute(gemm_tf32_kernel,
                         cudaFuncAttributeMaxDynamicSharedMemorySize, GEMM_SMEM);

    offset_conv_kernel<<<dim3(144, BB), 256>>>(x, w_off, b_off);
    prep_kernel<<<(BB * K9 * HWP + 255) / 256, 256>>>();
    pack_a_kernel<<<dim3(HWP / 32, CC / 32, BB), dim3(32, 8)>>>(x);
    pack_w_kernel<<<(K9 * CC * CC + 255) / 256, 256>>>(w_conv);
    gemm_tf32_kernel<<<dim3(HWP / 128, CC / 128, BB * K9), 128, GEMM_SMEM>>>();
    combine_kernel<<<dim3(HWP / 32, BB), 256>>>(x, b_conv, gamma, beta,
                                                run_mean, run_var, out);
}

// round 4
// speedup vs baseline: 2.7284x; 1.5290x over previous
#include <cuda_runtime.h>
#include <cuda_fp16.h>
#include <cstdint>

// Problem constants
#define BB 2
#define CC 256
#define HH 96
#define WW 96
#define HWP (HH*WW)          // 9216
#define K9 9
#define EPSBN 1e-5f

// ---------------- scratch (device globals; no dynamic allocation) -------------
__device__ float   g_om[BB * 27 * HWP];                 // offset conv output
__device__ int4    g_sidx[BB * K9 * HWP];               // 4 corner pixel indices
__device__ float4  g_sw[BB * K9 * HWP];                 // 4 bilinear weights * mask
__device__ __half2 g_Zh[(size_t)BB * K9 * HWP * CC / 2];// Z fp16 [bk][p][o]
__device__ float   g_A[(size_t)BB * HWP * CC];          // tf32 plain [b][p][c]
__device__ float   g_Apk[(size_t)BB * HWP * CC];        // frag-packed A
__device__ float   g_Bpk[(size_t)K9 * CC * CC];         // frag-packed w_conv
__device__ float   g_Woffpk[9 * 4 * 8 * 4 * 32 * 2];    // frag-packed w_off (o pad 32)

// ---------------- helpers ------------------------------------------------------
__device__ __forceinline__ uint32_t smem_u32(const void* p) {
    uint32_t a;
    asm("{ .reg .u64 t; cvta.to.shared.u64 t, %1; cvt.u32.u64 %0, t; }"
        : "=r"(a) : "l"(p));
    return a;
}
__device__ __forceinline__ float to_tf32(float x) {
    float y;
    asm("cvt.rna.tf32.f32 %0, %1;" : "=f"(y) : "f"(x));
    return y;
}
__device__ __forceinline__ void cp_async16(uint32_t s, const void* g) {
    asm volatile("cp.async.cg.shared.global [%0], [%1], 16;" :: "r"(s), "l"(g));
}
#define CP_COMMIT() asm volatile("cp.async.commit_group;" ::: "memory")
#define CP_WAIT0()  asm volatile("cp.async.wait_group 0;" ::: "memory")

__device__ __forceinline__ void mma_tf32(float* d, const uint32_t* a, const uint32_t* b) {
    asm volatile(
        "mma.sync.aligned.m16n8k8.row.col.f32.tf32.tf32.f32 "
        "{%0,%1,%2,%3}, {%4,%5,%6,%7}, {%8,%9}, {%0,%1,%2,%3};"
        : "+f"(d[0]), "+f"(d[1]), "+f"(d[2]), "+f"(d[3])
        : "r"(a[0]), "r"(a[1]), "r"(a[2]), "r"(a[3]), "r"(b[0]), "r"(b[1]));
}

// =============================================================================
// pack_a: transpose + tf32 round: x[b][c][p] -> g_A[b][p][c]
// =============================================================================
__global__ __launch_bounds__(256) void pack_a_kernel(const float* __restrict__ x)
{
    __shared__ float t[32][33];
    const int b  = blockIdx.z;
    const int p0 = blockIdx.x * 32;
    const int c0 = blockIdx.y * 32;
    const int tx = threadIdx.x, ty = threadIdx.y;   // (32, 8)

    const float* xb = x + ((size_t)b * CC + c0) * HWP + p0;
#pragma unroll
    for (int i = 0; i < 32; i += 8)
        t[ty + i][tx] = xb[(size_t)(ty + i) * HWP + tx];
    __syncthreads();

    float* A = g_A + ((size_t)b * HWP + p0) * CC + c0;
#pragma unroll
    for (int i = 0; i < 32; i += 8)
        A[(size_t)(ty + i) * CC + tx] = to_tf32(t[tx][ty + i]);
}

// =============================================================================
// pack_apk: g_A[b][p][c] -> fragment-packed g_Apk[b][pb][kb][lane][4]
//   e0=A[pb*16+gid][kb*8+qid], e1=+8row, e2=+4col, e3=both
// =============================================================================
__global__ __launch_bounds__(256) void pack_apk_kernel()
{
    __shared__ float s[16][260];
    const int b  = blockIdx.y;
    const int pb = blockIdx.x;          // 0..575
    const int tid = threadIdx.x;
    const int row = tid >> 4, j = tid & 15;

    const float* src = g_A + ((size_t)b * 576 + pb) * 16 * CC;
#pragma unroll
    for (int m = 0; m < 4; m++) {
        const int col4 = j + m * 16;
        *(float4*)&s[row][col4 * 4] = *(const float4*)&src[(size_t)row * CC + col4 * 4];
    }
    __syncthreads();

    const int warp = tid >> 5, lane = tid & 31;
    const int gid = lane >> 2, qid = lane & 3;
    float* dstb = g_Apk + ((size_t)b * 576 + pb) * 32 * 128;
#pragma unroll
    for (int ii = 0; ii < 4; ii++) {
        const int kb = warp * 4 + ii;
        float4 v;
        v.x = s[gid][kb * 8 + qid];
        v.y = s[gid + 8][kb * 8 + qid];
        v.z = s[gid][kb * 8 + qid + 4];
        v.w = s[gid + 8][kb * 8 + qid + 4];
        *(float4*)&dstb[(size_t)kb * 128 + lane * 4] = v;
    }
}

// =============================================================================
// pack_w: w_conv[o][c][3][3] -> frag-packed g_Bpk[k][nb][kb][lane][2]
//   e0=B[c=kb*8+qid][o=nb*8+gid], e1=c+4
// =============================================================================
__global__ void pack_w_kernel(const float* __restrict__ w_conv)
{
    const int u = blockIdx.x * blockDim.x + threadIdx.x;
    if (u >= 9 * 32768) return;
    const int k = u / 32768;
    const int r = u % 32768;
    const int nb = r / 1024;
    const int r2 = r % 1024;
    const int kb = r2 / 32;
    const int lane = r2 % 32;
    const int gid = lane >> 2, qid = lane & 3;
    const int o = nb * 8 + gid;
    const int c = kb * 8 + qid;
    float2 v;
    v.x = to_tf32(w_conv[((size_t)o * CC + c) * 9 + k]);
    v.y = to_tf32(w_conv[((size_t)o * CC + c + 4) * 9 + k]);
    *(float2*)&g_Bpk[(size_t)u * 2] = v;
}

// =============================================================================
// pack_woff: w_off[27][256][3][3] -> frag-packed g_Woffpk[k][cg][cb][nt][lane][2]
//   o padded to 32 with zeros
// =============================================================================
__global__ void pack_woff_kernel(const float* __restrict__ w_off)
{
    const int u = blockIdx.x * blockDim.x + threadIdx.x;
    if (u >= 36864) return;
    const int k  = u / 4096;
    const int r  = u % 4096;
    const int cg = r / 1024;
    const int r2 = r % 1024;
    const int cb = r2 / 128;
    const int r3 = r2 % 128;
    const int nt = r3 / 32;
    const int lane = r3 % 32;
    const int gid = lane >> 2, qid = lane & 3;
    const int o = nt * 8 + gid;
    const int c = cg * 64 + cb * 8 + qid;
    float2 v = make_float2(0.f, 0.f);
    if (o < 27) {
        v.x = to_tf32(w_off[((size_t)o * CC + c) * 9 + k]);
        v.y = to_tf32(w_off[((size_t)o * CC + c + 4) * 9 + k]);
    }
    *(float2*)&g_Woffpk[(size_t)u * 2] = v;
}

// =============================================================================
// offset_mma: om[b][27][h][x] = conv3x3(x, w_off) + b_off via tf32 MMA
// block = (h, b), 192 thr = 6 warps, warp = 16 x-pixels, M=96 N=32 K=2304
// =============================================================================
#define OC_SMEM ((3*98*68 + 8*4*32*2) * 4)   // 88160 bytes

__global__ __launch_bounds__(192) void offset_mma_kernel(const float* __restrict__ b_off)
{
    extern __shared__ __align__(16) float osm[];
    float* Asm = osm;                  // [3][98][68]
    float* Bsm = osm + 3 * 98 * 68;    // [8][4][32][2]

    const int tid = threadIdx.x;
    const int warp = tid >> 5, lane = tid & 31;
    const int gid = lane >> 2, qid = lane & 3;
    const int h = blockIdx.x, b = blockIdx.y;

    float acc[4][4];
#pragma unroll
    for (int nt = 0; nt < 4; nt++)
#pragma unroll
        for (int e = 0; e < 4; e++) acc[nt][e] = 0.f;

    for (int cg = 0; cg < 4; cg++) {
        __syncthreads();
        // load A' (3 halo-row blocks of 98 pixels x 64 channels, zero padded)
        for (int t = tid; t < 3 * 98 * 16; t += 192) {
            const int ky = t / (98 * 16);
            const int rr = t % (98 * 16);
            const int i = rr >> 4, j = rr & 15;
            const int hh = h + ky - 1;
            const int xx = i - 1;
            float4 v = make_float4(0.f, 0.f, 0.f, 0.f);
            if (hh >= 0 && hh < HH && xx >= 0 && xx < WW)
                v = *(const float4*)(g_A + ((size_t)b * HWP + hh * WW + xx) * CC
                                     + cg * 64 + j * 4);
            *(float4*)(Asm + (ky * 98 + i) * 68 + j * 4) = v;
        }
        __syncthreads();

        for (int k = 0; k < 9; k++) {
            const int ky = k / 3, kx = k % 3;
            __syncthreads();
            for (int t = tid; t < 512; t += 192)
                *(float4*)(Bsm + t * 4) =
                    *(const float4*)(g_Woffpk + (size_t)(k * 4 + cg) * 2048 + t * 4);
            __syncthreads();

            const float* Abase = Asm + (size_t)ky * 98 * 68;
#pragma unroll
            for (int ks = 0; ks < 8; ks++) {
                const int c0 = ks * 8 + qid;
                const float* ap = Abase + (warp * 16 + gid + kx) * 68 + c0;
                uint32_t a[4];
                a[0] = __float_as_uint(ap[0]);
                a[1] = __float_as_uint(ap[8 * 68]);
                a[2] = __float_as_uint(ap[4]);
                a[3] = __float_as_uint(ap[8 * 68 + 4]);
#pragma unroll
                for (int nt = 0; nt < 4; nt++) {
                    const float2 bv = *(const float2*)(Bsm + ((ks * 4 + nt) * 32 + lane) * 2);
                    uint32_t bf[2];
                    bf[0] = __float_as_uint(bv.x);
                    bf[1] = __float_as_uint(bv.y);
                    mma_tf32(acc[nt], a, bf);
                }
            }
        }
    }

    // store: x = warp*16 + gid (+8), o = nt*8 + qid*2 (+1)
#pragma unroll
    for (int nt = 0; nt < 4; nt++) {
#pragma unroll
        for (int e = 0; e < 4; e++) {
            const int o = nt * 8 + qid * 2 + (e & 1);
            const int xx = warp * 16 + gid + ((e >= 2) ? 8 : 0);
            if (o < 27)
                g_om[((size_t)b * 27 + o) * HWP + h * WW + xx] = acc[nt][e] + b_off[o];
        }
    }
}

// =============================================================================
// prep: per (b,k,p): sigmoid mask, corner indices + weights (mask folded in)
// =============================================================================
__global__ void prep_kernel()
{
    const int t = blockIdx.x * blockDim.x + threadIdx.x;
    if (t >= BB * K9 * HWP) return;
    const int p  = t % HWP;
    const int bk = t / HWP;
    const int k  = bk % K9;
    const int b  = bk / K9;

    const float* omb = g_om + (size_t)b * 27 * HWP;
    const float dy = omb[(2 * k) * HWP + p];
    const float dx = omb[(2 * k + 1) * HWP + p];
    const float mv = omb[(18 + k) * HWP + p];
    const float m  = 1.f / (1.f + expf(-mv));

    const int h = p / WW, w = p - h * WW;
    const float py = (float)h + (float)(k / 3 - 1) + dy;
    const float px = (float)w + (float)(k % 3 - 1) + dx;
    const float y0f = floorf(py), x0f = floorf(px);
    const float ly = py - y0f, lx = px - x0f;
    const int y0 = (int)y0f, x0 = (int)x0f;
    const int y1 = y0 + 1,   x1 = x0 + 1;

    const bool vy0 = (y0 >= 0) & (y0 < HH);
    const bool vy1 = (y1 >= 0) & (y1 < HH);
    const bool vx0 = (x0 >= 0) & (x0 < WW);
    const bool vx1 = (x1 >= 0) & (x1 < WW);
    const int y0c = min(max(y0, 0), HH - 1), y1c = min(max(y1, 0), HH - 1);
    const int x0c = min(max(x0, 0), WW - 1), x1c = min(max(x1, 0), WW - 1);

    int4 idx;
    idx.x = y0c * WW + x0c;
    idx.y = y0c * WW + x1c;
    idx.z = y1c * WW + x0c;
    idx.w = y1c * WW + x1c;
    float4 wt;
    wt.x = (1.f - ly) * (1.f - lx) * m * ((vy0 & vx0) ? 1.f : 0.f);
    wt.y = (1.f - ly) * lx         * m * ((vy0 & vx1) ? 1.f : 0.f);
    wt.z = ly * (1.f - lx)         * m * ((vy1 & vx0) ? 1.f : 0.f);
    wt.w = ly * lx                 * m * ((vy1 & vx1) ? 1.f : 0.f);

    g_sidx[t] = idx;
    g_sw[t]   = wt;
}

// =============================================================================
// gemm: Z[z][p][o] = sum_c A[b][p][c] * B[k][o][c], fp16 out
// BM=128 BN=128 BK=32, 128 thr (2x2 warps, 64x64 tiles), frag-packed smem
// =============================================================================
#define GEMM_SMEM 65536

__global__ __launch_bounds__(128, 2) void gemm_tf32_kernel()
{
    extern __shared__ __align__(16) char gsm[];
    const uint32_t sA0 = smem_u32(gsm);            // 2 x 16KB
    const uint32_t sB0 = sA0 + 32768;              // 2 x 16KB

    const int tid  = threadIdx.x;
    const int warp = tid >> 5;
    const int lane = tid & 31;
    const int gid  = lane >> 2;
    const int qid  = lane & 3;
    const int wy   = warp >> 1;          // 0..1 (m)
    const int wx   = warp & 1;           // 0..1 (n)

    const int pb0 = blockIdx.x * 8;      // 8 pb blocks (BM=128)
    const int nb0 = blockIdx.y * 16;     // 16 nb blocks (BN=128)
    const int z   = blockIdx.z;          // b*9 + k
    const int b   = z / K9, k = z % K9;

    const float* Abase = g_Apk + (size_t)b * HWP * CC;
    const float* Bbase = g_Bpk + (size_t)k * 65536;

    const int kbp  = (tid >> 5) & 3;     // for A chunks
    const int alane = tid & 31;
    const int bkbp = (tid >> 4) & 3;     // for B chunks
    const int bpair = tid & 15;
    const int bnb_h = tid >> 6;          // 0..1

    auto load_stage = [&](int s, int kc) {
        const uint32_t sa = sA0 + s * 16384;
        const uint32_t sb = sB0 + s * 16384;
#pragma unroll
        for (int it = 0; it < 8; it++) {
            // A: t = it*128+tid: pb'=it, kb'=(tid>>5)&3, lane=tid&31
            cp_async16(sa + (uint32_t)(it * 128 + tid) * 16,
                       Abase + ((size_t)(pb0 + it) * 32 + kc * 4 + kbp) * 128 + alane * 4);
            // B: t = it*128+tid: nb'=it*2+(tid>>6), kb'=(tid>>4)&3, pair=tid&15
            cp_async16(sb + (uint32_t)(it * 128 + tid) * 16,
                       Bbase + ((size_t)(nb0 + it * 2 + bnb_h) * 32 + kc * 4 + bkbp) * 64
                             + bpair * 4);
        }
        CP_COMMIT();
    };

    float acc[4][8][4];
#pragma unroll
    for (int mt = 0; mt < 4; mt++)
#pragma unroll
        for (int nt = 0; nt < 8; nt++)
#pragma unroll
            for (int e = 0; e < 4; e++) acc[mt][nt][e] = 0.f;

    load_stage(0, 0);
    CP_WAIT0();
    __syncthreads();

#pragma unroll 1
    for (int kc = 0; kc < 8; kc++) {
        const int cur = kc & 1;
        if (kc < 7) load_stage(cur ^ 1, kc + 1);

        const uint32_t sa = sA0 + cur * 16384;
        const uint32_t sb = sB0 + cur * 16384;

#pragma unroll
        for (int ks = 0; ks < 4; ks++) {
            uint32_t afr[4][4], bfr[8][2];
#pragma unroll
            for (int mt = 0; mt < 4; mt++) {
                const uint4 v = *(const uint4*)(gsm + (sa - sA0)
                    + ((wy * 4 + mt) * 4 + ks) * 512 + lane * 16);
                afr[mt][0] = v.x; afr[mt][1] = v.y; afr[mt][2] = v.z; afr[mt][3] = v.w;
            }
#pragma unroll
            for (int nt = 0; nt < 8; nt++) {
                const uint2 v = *(const uint2*)(gsm + 32768 + (sb - sB0)
                    + ((wx * 8 + nt) * 4 + ks) * 256 + lane * 8);
                bfr[nt][0] = v.x; bfr[nt][1] = v.y;
            }
#pragma unroll
            for (int mt = 0; mt < 4; mt++)
#pragma unroll
                for (int nt = 0; nt < 8; nt++)
                    mma_tf32(acc[mt][nt], afr[mt], bfr[nt]);
        }
        if (kc < 7) CP_WAIT0();
        __syncthreads();
    }

    // epilogue: fp16 store to g_Zh[z][p][o]
    const int n0 = nb0 * 8;
#pragma unroll
    for (int mt = 0; mt < 4; mt++) {
        const int row0 = pb0 * 16 + wy * 64 + mt * 16 + gid;
        __half2* z0 = g_Zh + ((size_t)z * HWP + row0) * 128
                    + (n0 + wx * 64) / 2 + qid;
        __half2* z1 = z0 + 8 * 128;
#pragma unroll
        for (int nt = 0; nt < 8; nt++) {
            z0[nt * 4] = __floats2half2_rn(acc[mt][nt][0], acc[mt][nt][1]);
            z1[nt * 4] = __floats2half2_rn(acc[mt][nt][2], acc[mt][nt][3]);
        }
    }
}

// =============================================================================
// combine: y[o,p] = sum_{k,j} w[k,j,p] * Zh[bk][idx][o]; BN+ReLU+residual
// =============================================================================
__global__ __launch_bounds__(256) void combine_kernel(
    const float* __restrict__ x, const float* __restrict__ b_conv,
    const float* __restrict__ gamma, const float* __restrict__ beta,
    const float* __restrict__ run_mean, const float* __restrict__ run_var,
    float* __restrict__ out)
{
    __shared__ int   sI[32][36];
    __shared__ float sWt[32][36];
    __shared__ float sA[256], sB[256];
    __shared__ float trans[256 * 33];

    const int b  = blockIdx.y;
    const int p0 = blockIdx.x * 32;
    const int tid = threadIdx.x;

    {
        const int o = tid;
        const float inv = rsqrtf(run_var[o] + EPSBN);
        const float a = inv * gamma[o];
        sA[o] = a;
        sB[o] = (b_conv[o] - run_mean[o]) * a + beta[o];
    }
    for (int i = tid; i < 32 * 9; i += 256) {
        const int px = i % 32;
        const int k  = i / 32;
        const size_t t = ((size_t)(b * K9 + k)) * HWP + p0 + px;
        *(int4*)&sI[px][k * 4]    = g_sidx[t];
        *(float4*)&sWt[px][k * 4] = g_sw[t];
    }
    __syncthreads();

    const int og  = tid & 7;
    const int pxl = tid >> 3;

    float acc[4][8];
#pragma unroll
    for (int t = 0; t < 4; t++)
#pragma unroll
        for (int e = 0; e < 8; e++) acc[t][e] = 0.f;

    for (int k = 0; k < K9; k++) {
        const uint4* Zk = reinterpret_cast<const uint4*>(g_Zh)
                        + ((size_t)(b * K9 + k)) * HWP * 32;
#pragma unroll
        for (int j = 0; j < 4; j++) {
            const int   idx = sI[pxl][k * 4 + j];
            const float wj  = sWt[pxl][k * 4 + j];
            const uint4* src = Zk + (size_t)idx * 32 + og;
#pragma unroll
            for (int t = 0; t < 4; t++) {
                const uint4 u = src[t * 8];   // bytes: og*16 + t*128
                const float2 f0 = __half22float2(*reinterpret_cast<const __half2*>(&u.x));
                const float2 f1 = __half22float2(*reinterpret_cast<const __half2*>(&u.y));
                const float2 f2 = __half22float2(*reinterpret_cast<const __half2*>(&u.z));
                const float2 f3 = __half22float2(*reinterpret_cast<const __half2*>(&u.w));
                acc[t][0] += wj * f0.x; acc[t][1] += wj * f0.y;
                acc[t][2] += wj * f1.x; acc[t][3] += wj * f1.y;
                acc[t][4] += wj * f2.x; acc[t][5] += wj * f2.y;
                acc[t][6] += wj * f3.x; acc[t][7] += wj * f3.y;
            }
        }
    }

    // transpose via smem (o = t*64 + og*8 + e)
#pragma unroll
    for (int t = 0; t < 4; t++)
#pragma unroll
        for (int e = 0; e < 8; e++) {
            const int o = t * 64 + og * 8 + e;
            trans[o * 33 + pxl] = acc[t][e];
        }
    __syncthreads();

    const float* xb = x + ((size_t)b * CC) * HWP;
    float* ob = out + ((size_t)b * CC) * HWP;
    for (int pass = 0; pass < 32; pass++) {
        const int o   = (tid >> 5) + pass * 8;
        const int pxi = tid & 31;
        float v = trans[o * 33 + pxi];
        v = fmaxf(v * sA[o] + sB[o], 0.f);
        const size_t gi = (size_t)o * HWP + p0 + pxi;
        ob[gi] = xb[gi] + v;
    }
}

// =============================================================================
extern "C" void kernel_launch(void* const* d_in, const int* in_sizes, int n_in,
                              void* d_out, int out_size)
{
    const float* x        = (const float*)d_in[0];
    const float* w_off    = (const float*)d_in[1];
    const float* b_off    = (const float*)d_in[2];
    const float* w_conv   = (const float*)d_in[3];
    const float* b_conv   = (const float*)d_in[4];
    const float* gamma    = (const float*)d_in[5];
    const float* beta     = (const float*)d_in[6];
    const float* run_mean = (const float*)d_in[7];
    const float* run_var  = (const float*)d_in[8];
    float* out = (float*)d_out;

    cudaFuncSetAttribute(gemm_tf32_kernel,
                         cudaFuncAttributeMaxDynamicSharedMemorySize, GEMM_SMEM);
    cudaFuncSetAttribute(offset_mma_kernel,
                         cudaFuncAttributeMaxDynamicSharedMemorySize, OC_SMEM);

    pack_a_kernel<<<dim3(HWP / 32, CC / 32, BB), dim3(32, 8)>>>(x);
    pack_apk_kernel<<<dim3(576, BB), 256>>>();
    pack_w_kernel<<<(9 * 32768 + 255) / 256, 256>>>(w_conv);
    pack_woff_kernel<<<(36864 + 255) / 256, 256>>>(w_off);
    offset_mma_kernel<<<dim3(HH, BB), 192, OC_SMEM>>>(b_off);
    prep_kernel<<<(BB * K9 * HWP + 255) / 256, 256>>>();
    gemm_tf32_kernel<<<dim3(HWP / 128, CC / 128, BB * K9), 128, GEMM_SMEM>>>();
    combine_kernel<<<dim3(HWP / 32, BB), 256>>>(x, b_conv, gamma, beta,
                                                run_mean, run_var, out);
}

// round 5
// speedup vs baseline: 3.3570x; 1.2304x over previous
#include <cuda_runtime.h>
#include <cuda_fp16.h>
#include <cstdint>

// Problem constants
#define BB 2
#define CC 256
#define HH 96
#define WW 96
#define HWP (HH*WW)          // 9216
#define K9 9
#define EPSBN 1e-5f

// ---------------- scratch (device globals; no dynamic allocation) -------------
__device__ float   g_om[BB * 27 * HWP];                 // offset conv output
__device__ int4    g_sidx[BB * K9 * HWP];               // 4 corner pixel indices
__device__ float4  g_sw[BB * K9 * HWP];                 // 4 bilinear weights * mask
__device__ __half2 g_Zh[(size_t)BB * K9 * HWP * CC / 2];// Z fp16 [bk][p][o]
__device__ float   g_A[(size_t)BB * HWP * CC];          // tf32 plain [b][p][c]
// fp16 fragment-packed GEMM operands (m16n8k16)
__device__ uint4   g_Apkh[(size_t)BB * 576 * 16 * 32];  // [b][pb][kb16][lane] (4xu32)
__device__ uint2   g_Bpkh[(size_t)K9 * 32 * 16 * 32];   // [k][nb][kb16][lane] (2xu32)
__device__ float   g_Woffpk[9 * 4 * 8 * 4 * 32 * 2];    // frag-packed w_off (tf32, o pad 32)

// ---------------- helpers ------------------------------------------------------
__device__ __forceinline__ uint32_t smem_u32(const void* p) {
    uint32_t a;
    asm("{ .reg .u64 t; cvta.to.shared.u64 t, %1; cvt.u32.u64 %0, t; }"
        : "=r"(a) : "l"(p));
    return a;
}
__device__ __forceinline__ float to_tf32(float x) {
    float y;
    asm("cvt.rna.tf32.f32 %0, %1;" : "=f"(y) : "f"(x));
    return y;
}
__device__ __forceinline__ void cp_async16(uint32_t s, const void* g) {
    asm volatile("cp.async.cg.shared.global [%0], [%1], 16;" :: "r"(s), "l"(g));
}
#define CP_COMMIT() asm volatile("cp.async.commit_group;" ::: "memory")
#define CP_WAIT0()  asm volatile("cp.async.wait_group 0;" ::: "memory")

__device__ __forceinline__ void mma_tf32(float* d, const uint32_t* a, const uint32_t* b) {
    asm volatile(
        "mma.sync.aligned.m16n8k8.row.col.f32.tf32.tf32.f32 "
        "{%0,%1,%2,%3}, {%4,%5,%6,%7}, {%8,%9}, {%0,%1,%2,%3};"
        : "+f"(d[0]), "+f"(d[1]), "+f"(d[2]), "+f"(d[3])
        : "r"(a[0]), "r"(a[1]), "r"(a[2]), "r"(a[3]), "r"(b[0]), "r"(b[1]));
}
__device__ __forceinline__ void mma_f16(float* d, const uint32_t* a, const uint32_t* b) {
    asm volatile(
        "mma.sync.aligned.m16n8k16.row.col.f32.f16.f16.f32 "
        "{%0,%1,%2,%3}, {%4,%5,%6,%7}, {%8,%9}, {%0,%1,%2,%3};"
        : "+f"(d[0]), "+f"(d[1]), "+f"(d[2]), "+f"(d[3])
        : "r"(a[0]), "r"(a[1]), "r"(a[2]), "r"(a[3]), "r"(b[0]), "r"(b[1]));
}
__device__ __forceinline__ uint32_t pack_h2(float a, float b) {
    const __half2 h = __floats2half2_rn(a, b);
    return *reinterpret_cast<const uint32_t*>(&h);
}

// =============================================================================
// pack_a: transpose + tf32 round: x[b][c][p] -> g_A[b][p][c]  (for offset conv)
// =============================================================================
__global__ __launch_bounds__(256) void pack_a_kernel(const float* __restrict__ x)
{
    __shared__ float t[32][33];
    const int b  = blockIdx.z;
    const int p0 = blockIdx.x * 32;
    const int c0 = blockIdx.y * 32;
    const int tx = threadIdx.x, ty = threadIdx.y;   // (32, 8)

    const float* xb = x + ((size_t)b * CC + c0) * HWP + p0;
#pragma unroll
    for (int i = 0; i < 32; i += 8)
        t[ty + i][tx] = xb[(size_t)(ty + i) * HWP + tx];
    __syncthreads();

    float* A = g_A + ((size_t)b * HWP + p0) * CC + c0;
#pragma unroll
    for (int i = 0; i < 32; i += 8)
        A[(size_t)(ty + i) * CC + tx] = to_tf32(t[tx][ty + i]);
}

// =============================================================================
// pack_apk: g_A[b][p][c] -> fp16 m16n8k16 A-fragments
//   g_Apkh[b][pb][kb][lane] = {(gid,q2),(gid,q2+1)},{(gid+8,..)},{(gid,q2+8..)},{(gid+8,q2+8..)}
// =============================================================================
__global__ __launch_bounds__(256) void pack_apk_kernel()
{
    __shared__ float s[16][260];
    const int b  = blockIdx.y;
    const int pb = blockIdx.x;          // 0..575
    const int tid = threadIdx.x;
    const int row = tid >> 4, j = tid & 15;

    const float* src = g_A + ((size_t)b * 576 + pb) * 16 * CC;
#pragma unroll
    for (int m = 0; m < 4; m++) {
        const int col4 = j + m * 16;
        *(float4*)&s[row][col4 * 4] = *(const float4*)&src[(size_t)row * CC + col4 * 4];
    }
    __syncthreads();

    const int warp = tid >> 5, lane = tid & 31;
    const int gid = lane >> 2, qid = lane & 3;
    uint4* dstb = g_Apkh + ((size_t)b * 576 + pb) * 16 * 32;
#pragma unroll
    for (int ii = 0; ii < 2; ii++) {
        const int kb = warp * 2 + ii;
        const int c = kb * 16 + qid * 2;
        uint4 v;
        v.x = pack_h2(s[gid][c],         s[gid][c + 1]);
        v.y = pack_h2(s[gid + 8][c],     s[gid + 8][c + 1]);
        v.z = pack_h2(s[gid][c + 8],     s[gid][c + 9]);
        v.w = pack_h2(s[gid + 8][c + 8], s[gid + 8][c + 9]);
        dstb[(size_t)kb * 32 + lane] = v;
    }
}

// =============================================================================
// pack_w: w_conv[o][c][3][3] -> fp16 n8k16 B-fragments g_Bpkh[k][nb][kb][lane]
//   reg0 = {(c=q2, n=gid),(c=q2+1, n)}, reg1 = {(c+8, n),(c+9, n)}
// =============================================================================
__global__ void pack_w_kernel(const float* __restrict__ w_conv)
{
    const int u = blockIdx.x * blockDim.x + threadIdx.x;
    if (u >= 9 * 32 * 16 * 32) return;
    const int k = u / (32 * 16 * 32);
    const int r = u % (32 * 16 * 32);
    const int nb = r / (16 * 32);
    const int r2 = r % (16 * 32);
    const int kb = r2 / 32;
    const int lane = r2 % 32;
    const int gid = lane >> 2, qid = lane & 3;
    const int o = nb * 8 + gid;
    const int c = kb * 16 + qid * 2;
    uint2 v;
    v.x = pack_h2(w_conv[((size_t)o * CC + c) * 9 + k],
                  w_conv[((size_t)o * CC + c + 1) * 9 + k]);
    v.y = pack_h2(w_conv[((size_t)o * CC + c + 8) * 9 + k],
                  w_conv[((size_t)o * CC + c + 9) * 9 + k]);
    g_Bpkh[u] = v;
}

// =============================================================================
// pack_woff: w_off[27][256][3][3] -> frag-packed tf32 (o padded to 32)
// =============================================================================
__global__ void pack_woff_kernel(const float* __restrict__ w_off)
{
    const int u = blockIdx.x * blockDim.x + threadIdx.x;
    if (u >= 36864) return;
    const int k  = u / 4096;
    const int r  = u % 4096;
    const int cg = r / 1024;
    const int r2 = r % 1024;
    const int cb = r2 / 128;
    const int r3 = r2 % 128;
    const int nt = r3 / 32;
    const int lane = r3 % 32;
    const int gid = lane >> 2, qid = lane & 3;
    const int o = nt * 8 + gid;
    const int c = cg * 64 + cb * 8 + qid;
    float2 v = make_float2(0.f, 0.f);
    if (o < 27) {
        v.x = to_tf32(w_off[((size_t)o * CC + c) * 9 + k]);
        v.y = to_tf32(w_off[((size_t)o * CC + c + 4) * 9 + k]);
    }
    *(float2*)&g_Woffpk[(size_t)u * 2] = v;
}

// =============================================================================
// offset_mma: om[b][27][h][x] = conv3x3(x, w_off) + b_off via tf32 MMA
// =============================================================================
#define OC_SMEM ((3*98*68 + 8*4*32*2) * 4)   // 88160 bytes

__global__ __launch_bounds__(192) void offset_mma_kernel(const float* __restrict__ b_off)
{
    extern __shared__ __align__(16) float osm[];
    float* Asm = osm;                  // [3][98][68]
    float* Bsm = osm + 3 * 98 * 68;    // [8][4][32][2]

    const int tid = threadIdx.x;
    const int warp = tid >> 5, lane = tid & 31;
    const int gid = lane >> 2, qid = lane & 3;
    const int h = blockIdx.x, b = blockIdx.y;

    float acc[4][4];
#pragma unroll
    for (int nt = 0; nt < 4; nt++)
#pragma unroll
        for (int e = 0; e < 4; e++) acc[nt][e] = 0.f;

    for (int cg = 0; cg < 4; cg++) {
        __syncthreads();
        for (int t = tid; t < 3 * 98 * 16; t += 192) {
            const int ky = t / (98 * 16);
            const int rr = t % (98 * 16);
            const int i = rr >> 4, j = rr & 15;
            const int hh = h + ky - 1;
            const int xx = i - 1;
            float4 v = make_float4(0.f, 0.f, 0.f, 0.f);
            if (hh >= 0 && hh < HH && xx >= 0 && xx < WW)
                v = *(const float4*)(g_A + ((size_t)b * HWP + hh * WW + xx) * CC
                                     + cg * 64 + j * 4);
            *(float4*)(Asm + (ky * 98 + i) * 68 + j * 4) = v;
        }
        __syncthreads();

        for (int k = 0; k < 9; k++) {
            const int ky = k / 3, kx = k % 3;
            __syncthreads();
            for (int t = tid; t < 512; t += 192)
                *(float4*)(Bsm + t * 4) =
                    *(const float4*)(g_Woffpk + (size_t)(k * 4 + cg) * 2048 + t * 4);
            __syncthreads();

            const float* Abase = Asm + (size_t)ky * 98 * 68;
#pragma unroll
            for (int ks = 0; ks < 8; ks++) {
                const int c0 = ks * 8 + qid;
                const float* ap = Abase + (warp * 16 + gid + kx) * 68 + c0;
                uint32_t a[4];
                a[0] = __float_as_uint(ap[0]);
                a[1] = __float_as_uint(ap[8 * 68]);
                a[2] = __float_as_uint(ap[4]);
                a[3] = __float_as_uint(ap[8 * 68 + 4]);
#pragma unroll
                for (int nt = 0; nt < 4; nt++) {
                    const float2 bv = *(const float2*)(Bsm + ((ks * 4 + nt) * 32 + lane) * 2);
                    uint32_t bf[2];
                    bf[0] = __float_as_uint(bv.x);
                    bf[1] = __float_as_uint(bv.y);
                    mma_tf32(acc[nt], a, bf);
                }
            }
        }
    }

#pragma unroll
    for (int nt = 0; nt < 4; nt++) {
#pragma unroll
        for (int e = 0; e < 4; e++) {
            const int o = nt * 8 + qid * 2 + (e & 1);
            const int xx = warp * 16 + gid + ((e >= 2) ? 8 : 0);
            if (o < 27)
                g_om[((size_t)b * 27 + o) * HWP + h * WW + xx] = acc[nt][e] + b_off[o];
        }
    }
}

// =============================================================================
// prep: per (b,k,p): sigmoid mask, corner indices + weights (mask folded in)
// =============================================================================
__global__ void prep_kernel()
{
    const int t = blockIdx.x * blockDim.x + threadIdx.x;
    if (t >= BB * K9 * HWP) return;
    const int p  = t % HWP;
    const int bk = t / HWP;
    const int k  = bk % K9;
    const int b  = bk / K9;

    const float* omb = g_om + (size_t)b * 27 * HWP;
    const float dy = omb[(2 * k) * HWP + p];
    const float dx = omb[(2 * k + 1) * HWP + p];
    const float mv = omb[(18 + k) * HWP + p];
    const float m  = 1.f / (1.f + expf(-mv));

    const int h = p / WW, w = p - h * WW;
    const float py = (float)h + (float)(k / 3 - 1) + dy;
    const float px = (float)w + (float)(k % 3 - 1) + dx;
    const float y0f = floorf(py), x0f = floorf(px);
    const float ly = py - y0f, lx = px - x0f;
    const int y0 = (int)y0f, x0 = (int)x0f;
    const int y1 = y0 + 1,   x1 = x0 + 1;

    const bool vy0 = (y0 >= 0) & (y0 < HH);
    const bool vy1 = (y1 >= 0) & (y1 < HH);
    const bool vx0 = (x0 >= 0) & (x0 < WW);
    const bool vx1 = (x1 >= 0) & (x1 < WW);
    const int y0c = min(max(y0, 0), HH - 1), y1c = min(max(y1, 0), HH - 1);
    const int x0c = min(max(x0, 0), WW - 1), x1c = min(max(x1, 0), WW - 1);

    int4 idx;
    idx.x = y0c * WW + x0c;
    idx.y = y0c * WW + x1c;
    idx.z = y1c * WW + x0c;
    idx.w = y1c * WW + x1c;
    float4 wt;
    wt.x = (1.f - ly) * (1.f - lx) * m * ((vy0 & vx0) ? 1.f : 0.f);
    wt.y = (1.f - ly) * lx         * m * ((vy0 & vx1) ? 1.f : 0.f);
    wt.z = ly * (1.f - lx)         * m * ((vy1 & vx0) ? 1.f : 0.f);
    wt.w = ly * lx                 * m * ((vy1 & vx1) ? 1.f : 0.f);

    g_sidx[t] = idx;
    g_sw[t]   = wt;
}

// =============================================================================
// gemm: Z[z][p][o] = sum_c A[b][p][c] * B[k][o][c], fp16 in, fp32 acc, fp16 out
// BM=128 BN=128 BK=64, 128 thr (2x2 warps, 64x64 tiles), m16n8k16, frag-packed
// smem: A stage 16KB (8 pb x 4 kb x 512B), B stage 16KB (16 nb x 4 kb x 256B)
// =============================================================================
#define GEMM_SMEM 65536

__global__ __launch_bounds__(128, 2) void gemm_f16_kernel()
{
    extern __shared__ __align__(16) char gsm[];
    char* sA = gsm;                      // 2 x 16KB
    char* sB = gsm + 32768;              // 2 x 16KB
    const uint32_t uA = smem_u32(sA);
    const uint32_t uB = smem_u32(sB);

    const int tid  = threadIdx.x;
    const int warp = tid >> 5;
    const int lane = tid & 31;
    const int gid  = lane >> 2;
    const int qid  = lane & 3;
    const int wy   = warp >> 1;          // 0..1 (m)
    const int wx   = warp & 1;           // 0..1 (n)

    const int pb0 = blockIdx.x * 8;      // 8 pb tiles (BM=128)
    const int nb0 = blockIdx.y * 16;     // 16 nb tiles (BN=128)
    const int z   = blockIdx.z;          // b*9 + k
    const int b   = z / K9, k = z % K9;

    const uint4* Abase = g_Apkh + (size_t)b * 576 * 16 * 32;
    const uint2* Bbase = g_Bpkh + (size_t)k * 32 * 16 * 32;

    // A load slots: t = it*128+tid -> pb'=it, kb'=(tid>>5)&3, lane'=tid&31
    const int akb = (tid >> 5) & 3;
    const int alane = tid & 31;
    // B load slots: u = it*128+tid -> nb'=it*2+(tid>>6), kb'=(tid>>4)&3, pair=tid&15
    const int bkb = (tid >> 4) & 3;
    const int bpair = tid & 15;
    const int bnbh = tid >> 6;           // 0..1

    auto load_stage = [&](int s, int kc) {
        const uint32_t sa = uA + s * 16384;
        const uint32_t sb = uB + s * 16384;
#pragma unroll
        for (int it = 0; it < 8; it++) {
            cp_async16(sa + (uint32_t)(it * 128 + tid) * 16,
                       Abase + ((size_t)(pb0 + it) * 16 + kc * 4 + akb) * 32 + alane);
            cp_async16(sb + (uint32_t)(it * 128 + tid) * 16,
                       Bbase + ((size_t)(nb0 + it * 2 + bnbh) * 16 + kc * 4 + bkb) * 32
                             + bpair * 2);
        }
        CP_COMMIT();
    };

    float acc[4][8][4];
#pragma unroll
    for (int mt = 0; mt < 4; mt++)
#pragma unroll
        for (int nt = 0; nt < 8; nt++)
#pragma unroll
            for (int e = 0; e < 4; e++) acc[mt][nt][e] = 0.f;

    load_stage(0, 0);
    CP_WAIT0();
    __syncthreads();

#pragma unroll 1
    for (int kc = 0; kc < 4; kc++) {
        const int cur = kc & 1;
        if (kc < 3) load_stage(cur ^ 1, kc + 1);

        char* ca = sA + cur * 16384;
        char* cb = sB + cur * 16384;

#pragma unroll
        for (int ks = 0; ks < 4; ks++) {
            uint32_t afr[4][4], bfr[8][2];
#pragma unroll
            for (int mt = 0; mt < 4; mt++) {
                const uint4 v = *(const uint4*)(ca
                    + (((wy * 4 + mt) * 4 + ks) * 32 + lane) * 16);
                afr[mt][0] = v.x; afr[mt][1] = v.y; afr[mt][2] = v.z; afr[mt][3] = v.w;
            }
#pragma unroll
            for (int nt = 0; nt < 8; nt++) {
                const uint2 v = *(const uint2*)(cb
                    + (((wx * 8 + nt) * 4 + ks) * 32 + lane) * 8);
                bfr[nt][0] = v.x; bfr[nt][1] = v.y;
            }
#pragma unroll
            for (int mt = 0; mt < 4; mt++)
#pragma unroll
                for (int nt = 0; nt < 8; nt++)
                    mma_f16(acc[mt][nt], afr[mt], bfr[nt]);
        }
        if (kc < 3) CP_WAIT0();
        __syncthreads();
    }

    // epilogue: fp16 store to g_Zh[z][p][o]
    const int n0 = nb0 * 8;
#pragma unroll
    for (int mt = 0; mt < 4; mt++) {
        const int row0 = pb0 * 16 + wy * 64 + mt * 16 + gid;
        __half2* z0 = g_Zh + ((size_t)z * HWP + row0) * 128
                    + (n0 + wx * 64) / 2 + qid;
        __half2* z1 = z0 + 8 * 128;
#pragma unroll
        for (int nt = 0; nt < 8; nt++) {
            z0[nt * 4] = __floats2half2_rn(acc[mt][nt][0], acc[mt][nt][1]);
            z1[nt * 4] = __floats2half2_rn(acc[mt][nt][2], acc[mt][nt][3]);
        }
    }
}

// =============================================================================
// combine: y[o,p] = sum_{k,j} w[k,j,p] * Zh[bk][idx][o]; BN+ReLU+residual
// =============================================================================
__global__ __launch_bounds__(256) void combine_kernel(
    const float* __restrict__ x, const float* __restrict__ b_conv,
    const float* __restrict__ gamma, const float* __restrict__ beta,
    const float* __restrict__ run_mean, const float* __restrict__ run_var,
    float* __restrict__ out)
{
    __shared__ int   sI[32][36];
    __shared__ float sWt[32][36];
    __shared__ float sA[256], sB[256];
    __shared__ float trans[256 * 33];

    const int b  = blockIdx.y;
    const int p0 = blockIdx.x * 32;
    const int tid = threadIdx.x;

    {
        const int o = tid;
        const float inv = rsqrtf(run_var[o] + EPSBN);
        const float a = inv * gamma[o];
        sA[o] = a;
        sB[o] = (b_conv[o] - run_mean[o]) * a + beta[o];
    }
    for (int i = tid; i < 32 * 9; i += 256) {
        const int px = i % 32;
        const int k  = i / 32;
        const size_t t = ((size_t)(b * K9 + k)) * HWP + p0 + px;
        *(int4*)&sI[px][k * 4]    = g_sidx[t];
        *(float4*)&sWt[px][k * 4] = g_sw[t];
    }
    __syncthreads();

    const int og  = tid & 7;
    const int pxl = tid >> 3;

    float acc[4][8];
#pragma unroll
    for (int t = 0; t < 4; t++)
#pragma unroll
        for (int e = 0; e < 8; e++) acc[t][e] = 0.f;

    for (int k = 0; k < K9; k++) {
        const uint4* Zk = reinterpret_cast<const uint4*>(g_Zh)
                        + ((size_t)(b * K9 + k)) * HWP * 32;
#pragma unroll
        for (int j = 0; j < 4; j++) {
            const int   idx = sI[pxl][k * 4 + j];
            const float wj  = sWt[pxl][k * 4 + j];
            const uint4* src = Zk + (size_t)idx * 32 + og;
#pragma unroll
            for (int t = 0; t < 4; t++) {
                const uint4 u = src[t * 8];
                const float2 f0 = __half22float2(*reinterpret_cast<const __half2*>(&u.x));
                const float2 f1 = __half22float2(*reinterpret_cast<const __half2*>(&u.y));
                const float2 f2 = __half22float2(*reinterpret_cast<const __half2*>(&u.z));
                const float2 f3 = __half22float2(*reinterpret_cast<const __half2*>(&u.w));
                acc[t][0] += wj * f0.x; acc[t][1] += wj * f0.y;
                acc[t][2] += wj * f1.x; acc[t][3] += wj * f1.y;
                acc[t][4] += wj * f2.x; acc[t][5] += wj * f2.y;
                acc[t][6] += wj * f3.x; acc[t][7] += wj * f3.y;
            }
        }
    }

#pragma unroll
    for (int t = 0; t < 4; t++)
#pragma unroll
        for (int e = 0; e < 8; e++) {
            const int o = t * 64 + og * 8 + e;
            trans[o * 33 + pxl] = acc[t][e];
        }
    __syncthreads();

    const float* xb = x + ((size_t)b * CC) * HWP;
    float* ob = out + ((size_t)b * CC) * HWP;
    for (int pass = 0; pass < 32; pass++) {
        const int o   = (tid >> 5) + pass * 8;
        const int pxi = tid & 31;
        float v = trans[o * 33 + pxi];
        v = fmaxf(v * sA[o] + sB[o], 0.f);
        const size_t gi = (size_t)o * HWP + p0 + pxi;
        ob[gi] = xb[gi] + v;
    }
}

// =============================================================================
extern "C" void kernel_launch(void* const* d_in, const int* in_sizes, int n_in,
                              void* d_out, int out_size)
{
    const float* x        = (const float*)d_in[0];
    const float* w_off    = (const float*)d_in[1];
    const float* b_off    = (const float*)d_in[2];
    const float* w_conv   = (const float*)d_in[3];
    const float* b_conv   = (const float*)d_in[4];
    const float* gamma    = (const float*)d_in[5];
    const float* beta     = (const float*)d_in[6];
    const float* run_mean = (const float*)d_in[7];
    const float* run_var  = (const float*)d_in[8];
    float* out = (float*)d_out;

    cudaFuncSetAttribute(gemm_f16_kernel,
                         cudaFuncAttributeMaxDynamicSharedMemorySize, GEMM_SMEM);
    cudaFuncSetAttribute(offset_mma_kernel,
                         cudaFuncAttributeMaxDynamicSharedMemorySize, OC_SMEM);

    pack_a_kernel<<<dim3(HWP / 32, CC / 32, BB), dim3(32, 8)>>>(x);
    pack_apk_kernel<<<dim3(576, BB), 256>>>();
    pack_w_kernel<<<(9 * 32 * 16 * 32 + 255) / 256, 256>>>(w_conv);
    pack_woff_kernel<<<(36864 + 255) / 256, 256>>>(w_off);
    offset_mma_kernel<<<dim3(HH, BB), 192, OC_SMEM>>>(b_off);
    prep_kernel<<<(BB * K9 * HWP + 255) / 256, 256>>>();
    gemm_f16_kernel<<<dim3(HWP / 128, CC / 128, BB * K9), 128, GEMM_SMEM>>>();
    combine_kernel<<<dim3(HWP / 32, BB), 256>>>(x, b_conv, gamma, beta,
                                                run_mean, run_var, out);
}

// round 6
// speedup vs baseline: 3.7282x; 1.1106x over previous
#include <cuda_runtime.h>
#include <cuda_fp16.h>
#include <cstdint>

// Problem constants
#define BB 2
#define CC 256
#define HH 96
#define WW 96
#define HWP (HH*WW)          // 9216
#define K9 9
#define EPSBN 1e-5f

// ---------------- scratch (device globals; no dynamic allocation) -------------
__device__ float   g_om[BB * 27 * HWP];                 // offset conv output
__device__ __half2 g_Zh[(size_t)BB * K9 * HWP * CC / 2];// Z fp16 [bk][p][o]
__device__ float   g_A[(size_t)BB * HWP * CC];          // tf32 plain [b][p][c]
// fp16 fragment-packed GEMM operands (m16n8k16)
__device__ uint4   g_Apkh[(size_t)BB * 576 * 16 * 32];  // [b][pb][kb16][lane] (4xu32)
__device__ uint2   g_Bpkh[(size_t)K9 * 32 * 16 * 32];   // [k][nb][kb16][lane] (2xu32)
__device__ float   g_Woffpk[9 * 4 * 8 * 4 * 32 * 2];    // frag-packed w_off (tf32, o pad 32)

// ---------------- helpers ------------------------------------------------------
__device__ __forceinline__ uint32_t smem_u32(const void* p) {
    uint32_t a;
    asm("{ .reg .u64 t; cvta.to.shared.u64 t, %1; cvt.u32.u64 %0, t; }"
        : "=r"(a) : "l"(p));
    return a;
}
__device__ __forceinline__ float to_tf32(float x) {
    float y;
    asm("cvt.rna.tf32.f32 %0, %1;" : "=f"(y) : "f"(x));
    return y;
}
__device__ __forceinline__ void cp_async16(uint32_t s, const void* g) {
    asm volatile("cp.async.cg.shared.global [%0], [%1], 16;" :: "r"(s), "l"(g));
}
#define CP_COMMIT() asm volatile("cp.async.commit_group;" ::: "memory")
#define CP_WAIT0()  asm volatile("cp.async.wait_group 0;" ::: "memory")

__device__ __forceinline__ void mma_tf32(float* d, const uint32_t* a, const uint32_t* b) {
    asm volatile(
        "mma.sync.aligned.m16n8k8.row.col.f32.tf32.tf32.f32 "
        "{%0,%1,%2,%3}, {%4,%5,%6,%7}, {%8,%9}, {%0,%1,%2,%3};"
        : "+f"(d[0]), "+f"(d[1]), "+f"(d[2]), "+f"(d[3])
        : "r"(a[0]), "r"(a[1]), "r"(a[2]), "r"(a[3]), "r"(b[0]), "r"(b[1]));
}
__device__ __forceinline__ void mma_f16(float* d, const uint32_t* a, const uint32_t* b) {
    asm volatile(
        "mma.sync.aligned.m16n8k16.row.col.f32.f16.f16.f32 "
        "{%0,%1,%2,%3}, {%4,%5,%6,%7}, {%8,%9}, {%0,%1,%2,%3};"
        : "+f"(d[0]), "+f"(d[1]), "+f"(d[2]), "+f"(d[3])
        : "r"(a[0]), "r"(a[1]), "r"(a[2]), "r"(a[3]), "r"(b[0]), "r"(b[1]));
}
__device__ __forceinline__ uint32_t pack_h2(float a, float b) {
    const __half2 h = __floats2half2_rn(a, b);
    return *reinterpret_cast<const uint32_t*>(&h);
}

// =============================================================================
// pack_a_fused: x[b][c][p] -> g_A[b][p][c] (tf32 fp32) + g_Apkh fp16 A-fragments
// block = 256 thr, handles 16 pixels (one pb) x 256 channels
// =============================================================================
__global__ __launch_bounds__(256) void pack_a_fused_kernel(const float* __restrict__ x)
{
    __shared__ float s[256][17];      // [c][p], pad 17
    const int b  = blockIdx.y;
    const int pb = blockIdx.x;        // 0..575
    const int p0 = pb * 16;
    const int tid = threadIdx.x;

    // load: thread = one channel row, 16 pixels
    {
        const float4* xr = (const float4*)(x + ((size_t)b * CC + tid) * HWP + p0);
        const float4 a0 = xr[0], a1 = xr[1], a2 = xr[2], a3 = xr[3];
        s[tid][0]  = a0.x; s[tid][1]  = a0.y; s[tid][2]  = a0.z; s[tid][3]  = a0.w;
        s[tid][4]  = a1.x; s[tid][5]  = a1.y; s[tid][6]  = a1.z; s[tid][7]  = a1.w;
        s[tid][8]  = a2.x; s[tid][9]  = a2.y; s[tid][10] = a2.z; s[tid][11] = a2.w;
        s[tid][12] = a3.x; s[tid][13] = a3.y; s[tid][14] = a3.z; s[tid][15] = a3.w;
    }
    __syncthreads();

    // write g_A[p][c] (tf32-rounded fp32) for offset conv
    {
        const int p  = tid >> 4;      // 0..15
        const int cq = tid & 15;      // 0..15 (16-channel chunk)
        float* Arow = g_A + ((size_t)b * HWP + p0 + p) * CC + cq * 16;
#pragma unroll
        for (int j = 0; j < 16; j += 4) {
            float4 v;
            v.x = to_tf32(s[cq * 16 + j][p]);
            v.y = to_tf32(s[cq * 16 + j + 1][p]);
            v.z = to_tf32(s[cq * 16 + j + 2][p]);
            v.w = to_tf32(s[cq * 16 + j + 3][p]);
            *(float4*)&Arow[j] = v;
        }
    }

    // write fp16 m16n8k16 A-fragments
    {
        const int warp = tid >> 5, lane = tid & 31;
        const int gid = lane >> 2, qid = lane & 3;
        uint4* dstb = g_Apkh + ((size_t)b * 576 + pb) * 16 * 32;
#pragma unroll
        for (int ii = 0; ii < 2; ii++) {
            const int kb = warp * 2 + ii;
            const int c = kb * 16 + qid * 2;
            uint4 v;
            v.x = pack_h2(s[c][gid],         s[c + 1][gid]);
            v.y = pack_h2(s[c][gid + 8],     s[c + 1][gid + 8]);
            v.z = pack_h2(s[c + 8][gid],     s[c + 9][gid]);
            v.w = pack_h2(s[c + 8][gid + 8], s[c + 9][gid + 8]);
            dstb[(size_t)kb * 32 + lane] = v;
        }
    }
}

// =============================================================================
// pack_weights: merged w_conv -> fp16 B-frags AND w_off -> tf32 frags (o pad 32)
// =============================================================================
#define NWCONV (9 * 32 * 16 * 32)     // 147456
#define NWOFF  36864

__global__ void pack_weights_kernel(const float* __restrict__ w_conv,
                                    const float* __restrict__ w_off)
{
    const int u = blockIdx.x * blockDim.x + threadIdx.x;
    if (u < NWCONV) {
        const int k = u / (32 * 16 * 32);
        const int r = u % (32 * 16 * 32);
        const int nb = r / (16 * 32);
        const int r2 = r % (16 * 32);
        const int kb = r2 / 32;
        const int lane = r2 % 32;
        const int gid = lane >> 2, qid = lane & 3;
        const int o = nb * 8 + gid;
        const int c = kb * 16 + qid * 2;
        uint2 v;
        v.x = pack_h2(w_conv[((size_t)o * CC + c) * 9 + k],
                      w_conv[((size_t)o * CC + c + 1) * 9 + k]);
        v.y = pack_h2(w_conv[((size_t)o * CC + c + 8) * 9 + k],
                      w_conv[((size_t)o * CC + c + 9) * 9 + k]);
        g_Bpkh[u] = v;
    } else if (u < NWCONV + NWOFF) {
        const int w = u - NWCONV;
        const int k  = w / 4096;
        const int r  = w % 4096;
        const int cg = r / 1024;
        const int r2 = r % 1024;
        const int cb = r2 / 128;
        const int r3 = r2 % 128;
        const int nt = r3 / 32;
        const int lane = r3 % 32;
        const int gid = lane >> 2, qid = lane & 3;
        const int o = nt * 8 + gid;
        const int c = cg * 64 + cb * 8 + qid;
        float2 v = make_float2(0.f, 0.f);
        if (o < 27) {
            v.x = to_tf32(w_off[((size_t)o * CC + c) * 9 + k]);
            v.y = to_tf32(w_off[((size_t)o * CC + c + 4) * 9 + k]);
        }
        *(float2*)&g_Woffpk[(size_t)w * 2] = v;
    }
}

// =============================================================================
// offset_mma: om[b][27][h][x] = conv3x3(x, w_off) + b_off via tf32 MMA
// =============================================================================
#define OC_SMEM ((3*98*68 + 8*4*32*2) * 4)   // 88160 bytes

__global__ __launch_bounds__(192) void offset_mma_kernel(const float* __restrict__ b_off)
{
    extern __shared__ __align__(16) float osm[];
    float* Asm = osm;                  // [3][98][68]
    float* Bsm = osm + 3 * 98 * 68;    // [8][4][32][2]

    const int tid = threadIdx.x;
    const int warp = tid >> 5, lane = tid & 31;
    const int gid = lane >> 2, qid = lane & 3;
    const int h = blockIdx.x, b = blockIdx.y;

    float acc[4][4];
#pragma unroll
    for (int nt = 0; nt < 4; nt++)
#pragma unroll
        for (int e = 0; e < 4; e++) acc[nt][e] = 0.f;

    for (int cg = 0; cg < 4; cg++) {
        __syncthreads();
        for (int t = tid; t < 3 * 98 * 16; t += 192) {
            const int ky = t / (98 * 16);
            const int rr = t % (98 * 16);
            const int i = rr >> 4, j = rr & 15;
            const int hh = h + ky - 1;
            const int xx = i - 1;
            float4 v = make_float4(0.f, 0.f, 0.f, 0.f);
            if (hh >= 0 && hh < HH && xx >= 0 && xx < WW)
                v = *(const float4*)(g_A + ((size_t)b * HWP + hh * WW + xx) * CC
                                     + cg * 64 + j * 4);
            *(float4*)(Asm + (ky * 98 + i) * 68 + j * 4) = v;
        }
        __syncthreads();

        for (int k = 0; k < 9; k++) {
            const int ky = k / 3, kx = k % 3;
            __syncthreads();
            for (int t = tid; t < 512; t += 192)
                *(float4*)(Bsm + t * 4) =
                    *(const float4*)(g_Woffpk + (size_t)(k * 4 + cg) * 2048 + t * 4);
            __syncthreads();

            const float* Abase = Asm + (size_t)ky * 98 * 68;
#pragma unroll
            for (int ks = 0; ks < 8; ks++) {
                const int c0 = ks * 8 + qid;
                const float* ap = Abase + (warp * 16 + gid + kx) * 68 + c0;
                uint32_t a[4];
                a[0] = __float_as_uint(ap[0]);
                a[1] = __float_as_uint(ap[8 * 68]);
                a[2] = __float_as_uint(ap[4]);
                a[3] = __float_as_uint(ap[8 * 68 + 4]);
#pragma unroll
                for (int nt = 0; nt < 4; nt++) {
                    const float2 bv = *(const float2*)(Bsm + ((ks * 4 + nt) * 32 + lane) * 2);
                    uint32_t bf[2];
                    bf[0] = __float_as_uint(bv.x);
                    bf[1] = __float_as_uint(bv.y);
                    mma_tf32(acc[nt], a, bf);
                }
            }
        }
    }

#pragma unroll
    for (int nt = 0; nt < 4; nt++) {
#pragma unroll
        for (int e = 0; e < 4; e++) {
            const int o = nt * 8 + qid * 2 + (e & 1);
            const int xx = warp * 16 + gid + ((e >= 2) ? 8 : 0);
            if (o < 27)
                g_om[((size_t)b * 27 + o) * HWP + h * WW + xx] = acc[nt][e] + b_off[o];
        }
    }
}

// =============================================================================
// gemm: Z[z][p][o] = sum_c A[b][p][c] * B[k][o][c], fp16 in, fp32 acc, fp16 out
// =============================================================================
#define GEMM_SMEM 65536

__global__ __launch_bounds__(128, 2) void gemm_f16_kernel()
{
    extern __shared__ __align__(16) char gsm[];
    char* sA = gsm;                      // 2 x 16KB
    char* sB = gsm + 32768;              // 2 x 16KB
    const uint32_t uA = smem_u32(sA);
    const uint32_t uB = smem_u32(sB);

    const int tid  = threadIdx.x;
    const int warp = tid >> 5;
    const int lane = tid & 31;
    const int gid  = lane >> 2;
    const int qid  = lane & 3;
    const int wy   = warp >> 1;
    const int wx   = warp & 1;

    const int pb0 = blockIdx.x * 8;
    const int nb0 = blockIdx.y * 16;
    const int z   = blockIdx.z;
    const int b   = z / K9, k = z % K9;

    const uint4* Abase = g_Apkh + (size_t)b * 576 * 16 * 32;
    const uint2* Bbase = g_Bpkh + (size_t)k * 32 * 16 * 32;

    const int akb = (tid >> 5) & 3;
    const int alane = tid & 31;
    const int bkb = (tid >> 4) & 3;
    const int bpair = tid & 15;
    const int bnbh = tid >> 6;

    auto load_stage = [&](int s, int kc) {
        const uint32_t sa = uA + s * 16384;
        const uint32_t sb = uB + s * 16384;
#pragma unroll
        for (int it = 0; it < 8; it++) {
            cp_async16(sa + (uint32_t)(it * 128 + tid) * 16,
                       Abase + ((size_t)(pb0 + it) * 16 + kc * 4 + akb) * 32 + alane);
            cp_async16(sb + (uint32_t)(it * 128 + tid) * 16,
                       Bbase + ((size_t)(nb0 + it * 2 + bnbh) * 16 + kc * 4 + bkb) * 32
                             + bpair * 2);
        }
        CP_COMMIT();
    };

    float acc[4][8][4];
#pragma unroll
    for (int mt = 0; mt < 4; mt++)
#pragma unroll
        for (int nt = 0; nt < 8; nt++)
#pragma unroll
            for (int e = 0; e < 4; e++) acc[mt][nt][e] = 0.f;

    load_stage(0, 0);
    CP_WAIT0();
    __syncthreads();

#pragma unroll 1
    for (int kc = 0; kc < 4; kc++) {
        const int cur = kc & 1;
        if (kc < 3) load_stage(cur ^ 1, kc + 1);

        char* ca = sA + cur * 16384;
        char* cb = sB + cur * 16384;

#pragma unroll
        for (int ks = 0; ks < 4; ks++) {
            uint32_t afr[4][4], bfr[8][2];
#pragma unroll
            for (int mt = 0; mt < 4; mt++) {
                const uint4 v = *(const uint4*)(ca
                    + (((wy * 4 + mt) * 4 + ks) * 32 + lane) * 16);
                afr[mt][0] = v.x; afr[mt][1] = v.y; afr[mt][2] = v.z; afr[mt][3] = v.w;
            }
#pragma unroll
            for (int nt = 0; nt < 8; nt++) {
                const uint2 v = *(const uint2*)(cb
                    + (((wx * 8 + nt) * 4 + ks) * 32 + lane) * 8);
                bfr[nt][0] = v.x; bfr[nt][1] = v.y;
            }
#pragma unroll
            for (int mt = 0; mt < 4; mt++)
#pragma unroll
                for (int nt = 0; nt < 8; nt++)
                    mma_f16(acc[mt][nt], afr[mt], bfr[nt]);
        }
        if (kc < 3) CP_WAIT0();
        __syncthreads();
    }

    const int n0 = nb0 * 8;
#pragma unroll
    for (int mt = 0; mt < 4; mt++) {
        const int row0 = pb0 * 16 + wy * 64 + mt * 16 + gid;
        __half2* z0 = g_Zh + ((size_t)z * HWP + row0) * 128
                    + (n0 + wx * 64) / 2 + qid;
        __half2* z1 = z0 + 8 * 128;
#pragma unroll
        for (int nt = 0; nt < 8; nt++) {
            z0[nt * 4] = __floats2half2_rn(acc[mt][nt][0], acc[mt][nt][1]);
            z1[nt * 4] = __floats2half2_rn(acc[mt][nt][2], acc[mt][nt][3]);
        }
    }
}

// =============================================================================
// combine (prep fused): compute sampling meta from g_om inline, gather Z fp16,
// BN+ReLU+residual.
// =============================================================================
__global__ __launch_bounds__(256) void combine_kernel(
    const float* __restrict__ x, const float* __restrict__ b_conv,
    const float* __restrict__ gamma, const float* __restrict__ beta,
    const float* __restrict__ run_mean, const float* __restrict__ run_var,
    float* __restrict__ out)
{
    __shared__ int   sI[32][36];
    __shared__ float sWt[32][36];
    __shared__ float sA[256], sB[256];
    __shared__ float trans[256 * 33];

    const int b  = blockIdx.y;
    const int p0 = blockIdx.x * 32;
    const int tid = threadIdx.x;

    {
        const int o = tid;
        const float inv = rsqrtf(run_var[o] + EPSBN);
        const float a = inv * gamma[o];
        sA[o] = a;
        sB[o] = (b_conv[o] - run_mean[o]) * a + beta[o];
    }

    // inline prep: 32 px * 9 k items
    const float* omb = g_om + (size_t)b * 27 * HWP;
    for (int i = tid; i < 32 * 9; i += 256) {
        const int px = i & 31;
        const int k  = i >> 5;
        const int p  = p0 + px;

        const float dy = omb[(2 * k) * HWP + p];
        const float dx = omb[(2 * k + 1) * HWP + p];
        const float mv = omb[(18 + k) * HWP + p];
        const float m  = 1.f / (1.f + expf(-mv));

        const int h = p / WW, w = p - h * WW;
        const float py = (float)h + (float)(k / 3 - 1) + dy;
        const float px_ = (float)w + (float)(k % 3 - 1) + dx;
        const float y0f = floorf(py), x0f = floorf(px_);
        const float ly = py - y0f, lx = px_ - x0f;
        const int y0 = (int)y0f, x0 = (int)x0f;
        const int y1 = y0 + 1,   x1 = x0 + 1;

        const bool vy0 = (y0 >= 0) & (y0 < HH);
        const bool vy1 = (y1 >= 0) & (y1 < HH);
        const bool vx0 = (x0 >= 0) & (x0 < WW);
        const bool vx1 = (x1 >= 0) & (x1 < WW);
        const int y0c = min(max(y0, 0), HH - 1), y1c = min(max(y1, 0), HH - 1);
        const int x0c = min(max(x0, 0), WW - 1), x1c = min(max(x1, 0), WW - 1);

        int4 idx;
        idx.x = y0c * WW + x0c;
        idx.y = y0c * WW + x1c;
        idx.z = y1c * WW + x0c;
        idx.w = y1c * WW + x1c;
        float4 wt;
        wt.x = (1.f - ly) * (1.f - lx) * m * ((vy0 & vx0) ? 1.f : 0.f);
        wt.y = (1.f - ly) * lx         * m * ((vy0 & vx1) ? 1.f : 0.f);
        wt.z = ly * (1.f - lx)         * m * ((vy1 & vx0) ? 1.f : 0.f);
        wt.w = ly * lx                 * m * ((vy1 & vx1) ? 1.f : 0.f);

        *(int4*)&sI[px][k * 4]    = idx;
        *(float4*)&sWt[px][k * 4] = wt;
    }
    __syncthreads();

    const int og  = tid & 7;
    const int pxl = tid >> 3;

    float acc[4][8];
#pragma unroll
    for (int t = 0; t < 4; t++)
#pragma unroll
        for (int e = 0; e < 8; e++) acc[t][e] = 0.f;

    for (int k = 0; k < K9; k++) {
        const uint4* Zk = reinterpret_cast<const uint4*>(g_Zh)
                        + ((size_t)(b * K9 + k)) * HWP * 32;
#pragma unroll
        for (int j = 0; j < 4; j++) {
            const int   idx = sI[pxl][k * 4 + j];
            const float wj  = sWt[pxl][k * 4 + j];
            const uint4* src = Zk + (size_t)idx * 32 + og;
#pragma unroll
            for (int t = 0; t < 4; t++) {
                const uint4 u = src[t * 8];
                const float2 f0 = __half22float2(*reinterpret_cast<const __half2*>(&u.x));
                const float2 f1 = __half22float2(*reinterpret_cast<const __half2*>(&u.y));
                const float2 f2 = __half22float2(*reinterpret_cast<const __half2*>(&u.z));
                const float2 f3 = __half22float2(*reinterpret_cast<const __half2*>(&u.w));
                acc[t][0] += wj * f0.x; acc[t][1] += wj * f0.y;
                acc[t][2] += wj * f1.x; acc[t][3] += wj * f1.y;
                acc[t][4] += wj * f2.x; acc[t][5] += wj * f2.y;
                acc[t][6] += wj * f3.x; acc[t][7] += wj * f3.y;
            }
        }
    }

#pragma unroll
    for (int t = 0; t < 4; t++)
#pragma unroll
        for (int e = 0; e < 8; e++) {
            const int o = t * 64 + og * 8 + e;
            trans[o * 33 + pxl] = acc[t][e];
        }
    __syncthreads();

    const float* xb = x + ((size_t)b * CC) * HWP;
    float* ob = out + ((size_t)b * CC) * HWP;
    for (int pass = 0; pass < 32; pass++) {
        const int o   = (tid >> 5) + pass * 8;
        const int pxi = tid & 31;
        float v = trans[o * 33 + pxi];
        v = fmaxf(v * sA[o] + sB[o], 0.f);
        const size_t gi = (size_t)o * HWP + p0 + pxi;
        ob[gi] = xb[gi] + v;
    }
}

// =============================================================================
extern "C" void kernel_launch(void* const* d_in, const int* in_sizes, int n_in,
                              void* d_out, int out_size)
{
    const float* x        = (const float*)d_in[0];
    const float* w_off    = (const float*)d_in[1];
    const float* b_off    = (const float*)d_in[2];
    const float* w_conv   = (const float*)d_in[3];
    const float* b_conv   = (const float*)d_in[4];
    const float* gamma    = (const float*)d_in[5];
    const float* beta     = (const float*)d_in[6];
    const float* run_mean = (const float*)d_in[7];
    const float* run_var  = (const float*)d_in[8];
    float* out = (float*)d_out;

    cudaFuncSetAttribute(gemm_f16_kernel,
                         cudaFuncAttributeMaxDynamicSharedMemorySize, GEMM_SMEM);
    cudaFuncSetAttribute(offset_mma_kernel,
                         cudaFuncAttributeMaxDynamicSharedMemorySize, OC_SMEM);

    pack_a_fused_kernel<<<dim3(576, BB), 256>>>(x);
    pack_weights_kernel<<<(NWCONV + NWOFF + 255) / 256, 256>>>(w_conv, w_off);
    offset_mma_kernel<<<dim3(HH, BB), 192, OC_SMEM>>>(b_off);
    gemm_f16_kernel<<<dim3(HWP / 128, CC / 128, BB * K9), 128, GEMM_SMEM>>>();
    combine_kernel<<<dim3(HWP / 32, BB), 256>>>(x, b_conv, gamma, beta,
                                                run_mean, run_var, out);
}

// round 7
// speedup vs baseline: 4.9702x; 1.3331x over previous
#include <cuda_runtime.h>
#include <cuda_fp16.h>
#include <cstdint>

// Problem constants
#define BB 2
#define CC 256
#define HH 96
#define WW 96
#define HWP (HH*WW)          // 9216
#define K9 9
#define EPSBN 1e-5f

// ---------------- scratch (device globals; no dynamic allocation) -------------
__device__ float   g_om[BB * 27 * HWP];                 // offset conv output
__device__ __half2 g_Zh[(size_t)BB * K9 * HWP * CC / 2];// Z fp16 [bk][p][o]
__device__ __half  g_Axh[(size_t)BB * HWP * CC];        // fp16 x transposed [b][p][c]
// fp16 fragment-packed GEMM operands (m16n8k16)
__device__ uint4   g_Apkh[(size_t)BB * 576 * 16 * 32];  // [b][pb][kb16][lane]
__device__ uint2   g_Bpkh[(size_t)K9 * 32 * 16 * 32];   // [k][nb][kb16][lane]
__device__ uint2   g_Woffh[9 * 4 * 4 * 4 * 32];         // fp16 frag w_off [k][cg][kb][nt][lane]

// ---------------- helpers ------------------------------------------------------
__device__ __forceinline__ uint32_t smem_u32(const void* p) {
    uint32_t a;
    asm("{ .reg .u64 t; cvta.to.shared.u64 t, %1; cvt.u32.u64 %0, t; }"
        : "=r"(a) : "l"(p));
    return a;
}
__device__ __forceinline__ void cp_async16(uint32_t s, const void* g) {
    asm volatile("cp.async.cg.shared.global [%0], [%1], 16;" :: "r"(s), "l"(g));
}
#define CP_COMMIT() asm volatile("cp.async.commit_group;" ::: "memory")
#define CP_WAIT0()  asm volatile("cp.async.wait_group 0;" ::: "memory")
#define CP_WAIT1()  asm volatile("cp.async.wait_group 1;" ::: "memory")

__device__ __forceinline__ void mma_f16(float* d, const uint32_t* a, const uint32_t* b) {
    asm volatile(
        "mma.sync.aligned.m16n8k16.row.col.f32.f16.f16.f32 "
        "{%0,%1,%2,%3}, {%4,%5,%6,%7}, {%8,%9}, {%0,%1,%2,%3};"
        : "+f"(d[0]), "+f"(d[1]), "+f"(d[2]), "+f"(d[3])
        : "r"(a[0]), "r"(a[1]), "r"(a[2]), "r"(a[3]), "r"(b[0]), "r"(b[1]));
}
__device__ __forceinline__ uint32_t pack_h2(float a, float b) {
    const __half2 h = __floats2half2_rn(a, b);
    return *reinterpret_cast<const uint32_t*>(&h);
}

// =============================================================================
// pack_a_fused: x[b][c][p] -> g_Axh fp16 [b][p][c]  +  g_Apkh fp16 A-fragments
// block = 256 thr, handles 16 pixels (one pb) x 256 channels
// =============================================================================
__global__ __launch_bounds__(256) void pack_a_fused_kernel(const float* __restrict__ x)
{
    __shared__ float s[256][17];      // [c][p], pad 17
    const int b  = blockIdx.y;
    const int pb = blockIdx.x;        // 0..575
    const int p0 = pb * 16;
    const int tid = threadIdx.x;

    {
        const float4* xr = (const float4*)(x + ((size_t)b * CC + tid) * HWP + p0);
        const float4 a0 = xr[0], a1 = xr[1], a2 = xr[2], a3 = xr[3];
        s[tid][0]  = a0.x; s[tid][1]  = a0.y; s[tid][2]  = a0.z; s[tid][3]  = a0.w;
        s[tid][4]  = a1.x; s[tid][5]  = a1.y; s[tid][6]  = a1.z; s[tid][7]  = a1.w;
        s[tid][8]  = a2.x; s[tid][9]  = a2.y; s[tid][10] = a2.z; s[tid][11] = a2.w;
        s[tid][12] = a3.x; s[tid][13] = a3.y; s[tid][14] = a3.z; s[tid][15] = a3.w;
    }
    __syncthreads();

    // write g_Axh[p][c] fp16 (for offset conv)
    {
        const int p  = tid >> 4;      // 0..15
        const int cq = tid & 15;      // 16-channel chunk
        uint32_t h2b[8];
#pragma unroll
        for (int j = 0; j < 8; j++)
            h2b[j] = pack_h2(s[cq * 16 + 2 * j][p], s[cq * 16 + 2 * j + 1][p]);
        uint4* dst = (uint4*)(g_Axh + ((size_t)b * HWP + p0 + p) * CC + cq * 16);
        dst[0] = make_uint4(h2b[0], h2b[1], h2b[2], h2b[3]);
        dst[1] = make_uint4(h2b[4], h2b[5], h2b[6], h2b[7]);
    }

    // write fp16 m16n8k16 A-fragments
    {
        const int warp = tid >> 5, lane = tid & 31;
        const int gid = lane >> 2, qid = lane & 3;
        uint4* dstb = g_Apkh + ((size_t)b * 576 + pb) * 16 * 32;
#pragma unroll
        for (int ii = 0; ii < 2; ii++) {
            const int kb = warp * 2 + ii;
            const int c = kb * 16 + qid * 2;
            uint4 v;
            v.x = pack_h2(s[c][gid],         s[c + 1][gid]);
            v.y = pack_h2(s[c][gid + 8],     s[c + 1][gid + 8]);
            v.z = pack_h2(s[c + 8][gid],     s[c + 9][gid]);
            v.w = pack_h2(s[c + 8][gid + 8], s[c + 9][gid + 8]);
            dstb[(size_t)kb * 32 + lane] = v;
        }
    }
}

// =============================================================================
// pack_weights: w_conv -> fp16 B-frags  AND  w_off -> fp16 frags (o pad 32)
// =============================================================================
#define NWCONV (9 * 32 * 16 * 32)     // 147456
#define NWOFF  (9 * 4 * 4 * 4 * 32)   // 18432

__global__ void pack_weights_kernel(const float* __restrict__ w_conv,
                                    const float* __restrict__ w_off)
{
    const int u = blockIdx.x * blockDim.x + threadIdx.x;
    if (u < NWCONV) {
        const int k = u / (32 * 16 * 32);
        const int r = u % (32 * 16 * 32);
        const int nb = r / (16 * 32);
        const int r2 = r % (16 * 32);
        const int kb = r2 / 32;
        const int lane = r2 % 32;
        const int gid = lane >> 2, qid = lane & 3;
        const int o = nb * 8 + gid;
        const int c = kb * 16 + qid * 2;
        uint2 v;
        v.x = pack_h2(w_conv[((size_t)o * CC + c) * 9 + k],
                      w_conv[((size_t)o * CC + c + 1) * 9 + k]);
        v.y = pack_h2(w_conv[((size_t)o * CC + c + 8) * 9 + k],
                      w_conv[((size_t)o * CC + c + 9) * 9 + k]);
        g_Bpkh[u] = v;
    } else if (u < NWCONV + NWOFF) {
        const int w = u - NWCONV;
        const int k  = w / 2048;
        const int r  = w % 2048;
        const int cg = r / 512;
        const int r2 = r % 512;
        const int kb = r2 / 128;
        const int r3 = r2 % 128;
        const int nt = r3 / 32;
        const int lane = r3 % 32;
        const int gid = lane >> 2, qid = lane & 3;
        const int o = nt * 8 + gid;
        const int c = cg * 64 + kb * 16 + qid * 2;
        uint2 v = make_uint2(0u, 0u);
        if (o < 27) {
            v.x = pack_h2(w_off[((size_t)o * CC + c) * 9 + k],
                          w_off[((size_t)o * CC + c + 1) * 9 + k]);
            v.y = pack_h2(w_off[((size_t)o * CC + c + 8) * 9 + k],
                          w_off[((size_t)o * CC + c + 9) * 9 + k]);
        }
        g_Woffh[w] = v;
    }
}

// =============================================================================
// offset_mma: om[b][27][h][x] = conv3x3(x, w_off) + b_off via fp16 MMA
// block = (h, b), 192 thr = 6 warps (16 x-pixels each), M=96 N=32 K=2304
// smem: A halo [3][98][72] fp16 + all-k B frags for one cg (9 x 512 uint2)
// =============================================================================
#define OC_RS 72
#define OC_ASM_BYTES (((3 * 98 * OC_RS * 2) + 15) & ~15)   // 42336 -> 42336 (16-mult)
#define OC_SMEM (OC_ASM_BYTES + 9 * 512 * 8)               // + 36864

__global__ __launch_bounds__(192) void offset_mma_kernel(const float* __restrict__ b_off)
{
    extern __shared__ __align__(16) char osm[];
    __half* Asm = (__half*)osm;                       // [3][98][OC_RS]
    uint2*  Bsm = (uint2*)(osm + OC_ASM_BYTES);       // [9][512]

    const int tid = threadIdx.x;
    const int warp = tid >> 5, lane = tid & 31;
    const int gid = lane >> 2, qid = lane & 3;
    const int h = blockIdx.x, b = blockIdx.y;

    float acc[4][4];
#pragma unroll
    for (int nt = 0; nt < 4; nt++)
#pragma unroll
        for (int e = 0; e < 4; e++) acc[nt][e] = 0.f;

    for (int cg = 0; cg < 4; cg++) {
        __syncthreads();
        // B frags for this cg, all 9 taps
        for (int t = tid; t < 9 * 512; t += 192)
            Bsm[t] = g_Woffh[(size_t)((t >> 9) * 4 + cg) * 512 + (t & 511)];
        // A halo: 3 x 98 rows x 64 fp16 channels
        for (int t = tid; t < 3 * 98 * 8; t += 192) {
            const int ky = t / (98 * 8);
            const int rr = t % (98 * 8);
            const int i = rr >> 3, j = rr & 7;
            const int hh = h + ky - 1;
            const int xx = i - 1;
            uint4 v = make_uint4(0u, 0u, 0u, 0u);
            if (hh >= 0 && hh < HH && xx >= 0 && xx < WW)
                v = *(const uint4*)(g_Axh + ((size_t)b * HWP + hh * WW + xx) * CC
                                    + cg * 64 + j * 8);
            *(uint4*)&Asm[(ky * 98 + i) * OC_RS + j * 8] = v;
        }
        __syncthreads();

        for (int k = 0; k < 9; k++) {
            const int ky = k / 3, kx = k % 3;
            const __half* Ab = Asm + (size_t)ky * 98 * OC_RS;
            const uint2* Bk = Bsm + k * 512;
            const int row = warp * 16 + gid + kx;
#pragma unroll
            for (int kb = 0; kb < 4; kb++) {
                const int c0 = kb * 16 + qid * 2;
                uint32_t a[4];
                a[0] = *(const uint32_t*)&Ab[row * OC_RS + c0];
                a[1] = *(const uint32_t*)&Ab[(row + 8) * OC_RS + c0];
                a[2] = *(const uint32_t*)&Ab[row * OC_RS + c0 + 8];
                a[3] = *(const uint32_t*)&Ab[(row + 8) * OC_RS + c0 + 8];
#pragma unroll
                for (int nt = 0; nt < 4; nt++) {
                    const uint2 bv = Bk[(kb * 4 + nt) * 32 + lane];
                    uint32_t bf[2] = { bv.x, bv.y };
                    mma_f16(acc[nt], a, bf);
                }
            }
        }
    }

#pragma unroll
    for (int nt = 0; nt < 4; nt++) {
#pragma unroll
        for (int e = 0; e < 4; e++) {
            const int o = nt * 8 + qid * 2 + (e & 1);
            const int xx = warp * 16 + gid + ((e >= 2) ? 8 : 0);
            if (o < 27)
                g_om[((size_t)b * 27 + o) * HWP + h * WW + xx] = acc[nt][e] + b_off[o];
        }
    }
}

// =============================================================================
// gemm: Z[z][p][o] = sum_c A[b][p][c]*B[k][o][c]; fp16 in, fp32 acc, fp16 out
// BM=128 BN=128 BK=64, 128 thr (2x2 warps, 64x64), 3-stage cp.async pipeline
// stage s: A at gsm + s*32KB (16KB), B at +16KB (16KB)
// =============================================================================
#define GEMM_SMEM 98304

__global__ __launch_bounds__(128, 2) void gemm_f16_kernel()
{
    extern __shared__ __align__(16) char gsm[];
    const uint32_t u0 = smem_u32(gsm);

    const int tid  = threadIdx.x;
    const int warp = tid >> 5;
    const int lane = tid & 31;
    const int gid  = lane >> 2;
    const int qid  = lane & 3;
    const int wy   = warp >> 1;
    const int wx   = warp & 1;

    const int pb0 = blockIdx.x * 8;
    const int nb0 = blockIdx.y * 16;
    const int z   = blockIdx.z;
    const int b   = z / K9, k = z % K9;

    const uint4* Abase = g_Apkh + (size_t)b * 576 * 16 * 32;
    const uint2* Bbase = g_Bpkh + (size_t)k * 32 * 16 * 32;

    const int akb = (tid >> 5) & 3;
    const int alane = tid & 31;
    const int bkb = (tid >> 4) & 3;
    const int bpair = tid & 15;
    const int bnbh = tid >> 6;

    auto load_stage = [&](int s, int kc) {
        const uint32_t sa = u0 + s * 32768;
        const uint32_t sb = sa + 16384;
#pragma unroll
        for (int it = 0; it < 8; it++) {
            cp_async16(sa + (uint32_t)(it * 128 + tid) * 16,
                       Abase + ((size_t)(pb0 + it) * 16 + kc * 4 + akb) * 32 + alane);
            cp_async16(sb + (uint32_t)(it * 128 + tid) * 16,
                       Bbase + ((size_t)(nb0 + it * 2 + bnbh) * 16 + kc * 4 + bkb) * 32
                             + bpair * 2);
        }
        CP_COMMIT();
    };

    float acc[4][8][4];
#pragma unroll
    for (int mt = 0; mt < 4; mt++)
#pragma unroll
        for (int nt = 0; nt < 8; nt++)
#pragma unroll
            for (int e = 0; e < 4; e++) acc[mt][nt][e] = 0.f;

    load_stage(0, 0);
    load_stage(1, 1);

#pragma unroll 1
    for (int kc = 0; kc < 4; kc++) {
        if (kc < 3) { CP_WAIT1(); } else { CP_WAIT0(); }
        __syncthreads();
        if (kc < 2) load_stage((kc + 2) % 3, kc + 2);

        char* ca = gsm + (kc % 3) * 32768;
        char* cb = ca + 16384;

#pragma unroll
        for (int ks = 0; ks < 4; ks++) {
            uint32_t afr[4][4], bfr[8][2];
#pragma unroll
            for (int mt = 0; mt < 4; mt++) {
                const uint4 v = *(const uint4*)(ca
                    + (((wy * 4 + mt) * 4 + ks) * 32 + lane) * 16);
                afr[mt][0] = v.x; afr[mt][1] = v.y; afr[mt][2] = v.z; afr[mt][3] = v.w;
            }
#pragma unroll
            for (int nt = 0; nt < 8; nt++) {
                const uint2 v = *(const uint2*)(cb
                    + (((wx * 8 + nt) * 4 + ks) * 32 + lane) * 8);
                bfr[nt][0] = v.x; bfr[nt][1] = v.y;
            }
#pragma unroll
            for (int mt = 0; mt < 4; mt++)
#pragma unroll
                for (int nt = 0; nt < 8; nt++)
                    mma_f16(acc[mt][nt], afr[mt], bfr[nt]);
        }
    }

    // epilogue: stage fp16 tile in smem (row pad 132 half2), then coalesced store
    __syncthreads();
    __half2* st = (__half2*)gsm;
#pragma unroll
    for (int mt = 0; mt < 4; mt++) {
        const int r0 = wy * 64 + mt * 16 + gid;
#pragma unroll
        for (int nt = 0; nt < 8; nt++) {
            const int n2 = wx * 32 + nt * 4 + qid;
            st[r0 * 132 + n2]       = __floats2half2_rn(acc[mt][nt][0], acc[mt][nt][1]);
            st[(r0 + 8) * 132 + n2] = __floats2half2_rn(acc[mt][nt][2], acc[mt][nt][3]);
        }
    }
    __syncthreads();

    uint4* Z4 = (uint4*)g_Zh;
#pragma unroll
    for (int it = 0; it < 16; it++) {
        const int idx = it * 128 + tid;
        const int row = idx >> 4;
        const int ch  = idx & 15;
        const uint4 v = *(const uint4*)(gsm + row * 528 + ch * 16);
        Z4[((size_t)z * HWP + pb0 * 16 + row) * 32 + nb0 + ch] = v;
    }
}

// =============================================================================
// combine (prep fused): sampling meta from g_om inline, gather Z fp16,
// BN+ReLU+residual.
// =============================================================================
__global__ __launch_bounds__(256) void combine_kernel(
    const float* __restrict__ x, const float* __restrict__ b_conv,
    const float* __restrict__ gamma, const float* __restrict__ beta,
    const float* __restrict__ run_mean, const float* __restrict__ run_var,
    float* __restrict__ out)
{
    __shared__ int   sI[32][36];
    __shared__ float sWt[32][36];
    __shared__ float sA[256], sB[256];
    __shared__ float trans[256 * 33];

    const int b  = blockIdx.y;
    const int p0 = blockIdx.x * 32;
    const int tid = threadIdx.x;

    {
        const int o = tid;
        const float inv = rsqrtf(run_var[o] + EPSBN);
        const float a = inv * gamma[o];
        sA[o] = a;
        sB[o] = (b_conv[o] - run_mean[o]) * a + beta[o];
    }

    const float* omb = g_om + (size_t)b * 27 * HWP;
    for (int i = tid; i < 32 * 9; i += 256) {
        const int px = i & 31;
        const int k  = i >> 5;
        const int p  = p0 + px;

        const float dy = omb[(2 * k) * HWP + p];
        const float dx = omb[(2 * k + 1) * HWP + p];
        const float mv = omb[(18 + k) * HWP + p];
        const float m  = 1.f / (1.f + expf(-mv));

        const int h = p / WW, w = p - h * WW;
        const float py = (float)h + (float)(k / 3 - 1) + dy;
        const float px_ = (float)w + (float)(k % 3 - 1) + dx;
        const float y0f = floorf(py), x0f = floorf(px_);
        const float ly = py - y0f, lx = px_ - x0f;
        const int y0 = (int)y0f, x0 = (int)x0f;
        const int y1 = y0 + 1,   x1 = x0 + 1;

        const bool vy0 = (y0 >= 0) & (y0 < HH);
        const bool vy1 = (y1 >= 0) & (y1 < HH);
        const bool vx0 = (x0 >= 0) & (x0 < WW);
        const bool vx1 = (x1 >= 0) & (x1 < WW);
        const int y0c = min(max(y0, 0), HH - 1), y1c = min(max(y1, 0), HH - 1);
        const int x0c = min(max(x0, 0), WW - 1), x1c = min(max(x1, 0), WW - 1);

        int4 idx;
        idx.x = y0c * WW + x0c;
        idx.y = y0c * WW + x1c;
        idx.z = y1c * WW + x0c;
        idx.w = y1c * WW + x1c;
        float4 wt;
        wt.x = (1.f - ly) * (1.f - lx) * m * ((vy0 & vx0) ? 1.f : 0.f);
        wt.y = (1.f - ly) * lx         * m * ((vy0 & vx1) ? 1.f : 0.f);
        wt.z = ly * (1.f - lx)         * m * ((vy1 & vx0) ? 1.f : 0.f);
        wt.w = ly * lx                 * m * ((vy1 & vx1) ? 1.f : 0.f);

        *(int4*)&sI[px][k * 4]    = idx;
        *(float4*)&sWt[px][k * 4] = wt;
    }
    __syncthreads();

    const int og  = tid & 7;
    const int pxl = tid >> 3;

    float acc[4][8];
#pragma unroll
    for (int t = 0; t < 4; t++)
#pragma unroll
        for (int e = 0; e < 8; e++) acc[t][e] = 0.f;

    for (int k = 0; k < K9; k++) {
        const uint4* Zk = reinterpret_cast<const uint4*>(g_Zh)
                        + ((size_t)(b * K9 + k)) * HWP * 32;
#pragma unroll
        for (int j = 0; j < 4; j++) {
            const int   idx = sI[pxl][k * 4 + j];
            const float wj  = sWt[pxl][k * 4 + j];
            const uint4* src = Zk + (size_t)idx * 32 + og;
#pragma unroll
            for (int t = 0; t < 4; t++) {
                const uint4 u = src[t * 8];
                const float2 f0 = __half22float2(*reinterpret_cast<const __half2*>(&u.x));
                const float2 f1 = __half22float2(*reinterpret_cast<const __half2*>(&u.y));
                const float2 f2 = __half22float2(*reinterpret_cast<const __half2*>(&u.z));
                const float2 f3 = __half22float2(*reinterpret_cast<const __half2*>(&u.w));
                acc[t][0] += wj * f0.x; acc[t][1] += wj * f0.y;
                acc[t][2] += wj * f1.x; acc[t][3] += wj * f1.y;
                acc[t][4] += wj * f2.x; acc[t][5] += wj * f2.y;
                acc[t][6] += wj * f3.x; acc[t][7] += wj * f3.y;
            }
        }
    }

#pragma unroll
    for (int t = 0; t < 4; t++)
#pragma unroll
        for (int e = 0; e < 8; e++) {
            const int o = t * 64 + og * 8 + e;
            trans[o * 33 + pxl] = acc[t][e];
        }
    __syncthreads();

    const float* xb = x + ((size_t)b * CC) * HWP;
    float* ob = out + ((size_t)b * CC) * HWP;
    for (int pass = 0; pass < 32; pass++) {
        const int o   = (tid >> 5) + pass * 8;
        const int pxi = tid & 31;
        float v = trans[o * 33 + pxi];
        v = fmaxf(v * sA[o] + sB[o], 0.f);
        const size_t gi = (size_t)o * HWP + p0 + pxi;
        ob[gi] = xb[gi] + v;
    }
}

// =============================================================================
extern "C" void kernel_launch(void* const* d_in, const int* in_sizes, int n_in,
                              void* d_out, int out_size)
{
    const float* x        = (const float*)d_in[0];
    const float* w_off    = (const float*)d_in[1];
    const float* b_off    = (const float*)d_in[2];
    const float* w_conv   = (const float*)d_in[3];
    const float* b_conv   = (const float*)d_in[4];
    const float* gamma    = (const float*)d_in[5];
    const float* beta     = (const float*)d_in[6];
    const float* run_mean = (const float*)d_in[7];
    const float* run_var  = (const float*)d_in[8];
    float* out = (float*)d_out;

    cudaFuncSetAttribute(gemm_f16_kernel,
                         cudaFuncAttributeMaxDynamicSharedMemorySize, GEMM_SMEM);
    cudaFuncSetAttribute(offset_mma_kernel,
                         cudaFuncAttributeMaxDynamicSharedMemorySize, OC_SMEM);

    pack_a_fused_kernel<<<dim3(576, BB), 256>>>(x);
    pack_weights_kernel<<<(NWCONV + NWOFF + 255) / 256, 256>>>(w_conv, w_off);
    offset_mma_kernel<<<dim3(HH, BB), 192, OC_SMEM>>>(b_off);
    gemm_f16_kernel<<<dim3(HWP / 128, CC / 128, BB * K9), 128, GEMM_SMEM>>>();
    combine_kernel<<<dim3(HWP / 32, BB), 256>>>(x, b_conv, gamma, beta,
                                                run_mean, run_var, out);
}

// round 8
// speedup vs baseline: 4.9723x; 1.0004x over previous
#include <cuda_runtime.h>
#include <cuda_fp16.h>
#include <cstdint>

// Problem constants
#define BB 2
#define CC 256
#define HH 96
#define WW 96
#define HWP (HH*WW)          // 9216
#define K9 9
#define EPSBN 1e-5f

// ---------------- scratch (device globals; no dynamic allocation) -------------
__device__ float   g_om[BB * 27 * HWP];                 // offset conv output
__device__ __half2 g_Zh[(size_t)BB * K9 * HWP * CC / 2];// Z fp16 [bk][p][o]
__device__ __half  g_Axh[(size_t)BB * HWP * CC];        // fp16 x transposed [b][p][c]
// fp16 fragment-packed GEMM operands (m16n8k16)
__device__ uint4   g_Apkh[(size_t)BB * 576 * 16 * 32];  // [b][pb][kb16][lane]
__device__ uint2   g_Bpkh[(size_t)K9 * 32 * 16 * 32];   // [k][nb][kb16][lane]
__device__ uint2   g_Woffh[9 * 4 * 4 * 4 * 32];         // fp16 frag w_off [k][cg][kb][nt][lane]

// ---------------- helpers ------------------------------------------------------
__device__ __forceinline__ uint32_t smem_u32(const void* p) {
    uint32_t a;
    asm("{ .reg .u64 t; cvta.to.shared.u64 t, %1; cvt.u32.u64 %0, t; }"
        : "=r"(a) : "l"(p));
    return a;
}
__device__ __forceinline__ void cp_async16(uint32_t s, const void* g) {
    asm volatile("cp.async.cg.shared.global [%0], [%1], 16;" :: "r"(s), "l"(g));
}
#define CP_COMMIT() asm volatile("cp.async.commit_group;" ::: "memory")
#define CP_WAIT0()  asm volatile("cp.async.wait_group 0;" ::: "memory")
#define CP_WAIT1()  asm volatile("cp.async.wait_group 1;" ::: "memory")

__device__ __forceinline__ void mma_f16(float* d, const uint32_t* a, const uint32_t* b) {
    asm volatile(
        "mma.sync.aligned.m16n8k16.row.col.f32.f16.f16.f32 "
        "{%0,%1,%2,%3}, {%4,%5,%6,%7}, {%8,%9}, {%0,%1,%2,%3};"
        : "+f"(d[0]), "+f"(d[1]), "+f"(d[2]), "+f"(d[3])
        : "r"(a[0]), "r"(a[1]), "r"(a[2]), "r"(a[3]), "r"(b[0]), "r"(b[1]));
}
__device__ __forceinline__ uint32_t pack_h2(float a, float b) {
    const __half2 h = __floats2half2_rn(a, b);
    return *reinterpret_cast<const uint32_t*>(&h);
}

// =============================================================================
// pack_a_fused: x[b][c][p] -> g_Axh fp16 [b][p][c]  +  g_Apkh fp16 A-fragments
// =============================================================================
__global__ __launch_bounds__(256) void pack_a_fused_kernel(const float* __restrict__ x)
{
    __shared__ float s[256][17];      // [c][p], pad 17
    const int b  = blockIdx.y;
    const int pb = blockIdx.x;        // 0..575
    const int p0 = pb * 16;
    const int tid = threadIdx.x;

    {
        const float4* xr = (const float4*)(x + ((size_t)b * CC + tid) * HWP + p0);
        const float4 a0 = xr[0], a1 = xr[1], a2 = xr[2], a3 = xr[3];
        s[tid][0]  = a0.x; s[tid][1]  = a0.y; s[tid][2]  = a0.z; s[tid][3]  = a0.w;
        s[tid][4]  = a1.x; s[tid][5]  = a1.y; s[tid][6]  = a1.z; s[tid][7]  = a1.w;
        s[tid][8]  = a2.x; s[tid][9]  = a2.y; s[tid][10] = a2.z; s[tid][11] = a2.w;
        s[tid][12] = a3.x; s[tid][13] = a3.y; s[tid][14] = a3.z; s[tid][15] = a3.w;
    }
    __syncthreads();

    // write g_Axh[p][c] fp16 (for offset conv)
    {
        const int p  = tid >> 4;
        const int cq = tid & 15;
        uint32_t h2b[8];
#pragma unroll
        for (int j = 0; j < 8; j++)
            h2b[j] = pack_h2(s[cq * 16 + 2 * j][p], s[cq * 16 + 2 * j + 1][p]);
        uint4* dst = (uint4*)(g_Axh + ((size_t)b * HWP + p0 + p) * CC + cq * 16);
        dst[0] = make_uint4(h2b[0], h2b[1], h2b[2], h2b[3]);
        dst[1] = make_uint4(h2b[4], h2b[5], h2b[6], h2b[7]);
    }

    // write fp16 m16n8k16 A-fragments
    {
        const int warp = tid >> 5, lane = tid & 31;
        const int gid = lane >> 2, qid = lane & 3;
        uint4* dstb = g_Apkh + ((size_t)b * 576 + pb) * 16 * 32;
#pragma unroll
        for (int ii = 0; ii < 2; ii++) {
            const int kb = warp * 2 + ii;
            const int c = kb * 16 + qid * 2;
            uint4 v;
            v.x = pack_h2(s[c][gid],         s[c + 1][gid]);
            v.y = pack_h2(s[c][gid + 8],     s[c + 1][gid + 8]);
            v.z = pack_h2(s[c + 8][gid],     s[c + 9][gid]);
            v.w = pack_h2(s[c + 8][gid + 8], s[c + 9][gid + 8]);
            dstb[(size_t)kb * 32 + lane] = v;
        }
    }
}

// =============================================================================
// pack_weights: w_conv -> fp16 B-frags  AND  w_off -> fp16 frags (o pad 32)
// =============================================================================
#define NWCONV (9 * 32 * 16 * 32)     // 147456
#define NWOFF  (9 * 4 * 4 * 4 * 32)   // 18432

__global__ void pack_weights_kernel(const float* __restrict__ w_conv,
                                    const float* __restrict__ w_off)
{
    const int u = blockIdx.x * blockDim.x + threadIdx.x;
    if (u < NWCONV) {
        const int k = u / (32 * 16 * 32);
        const int r = u % (32 * 16 * 32);
        const int nb = r / (16 * 32);
        const int r2 = r % (16 * 32);
        const int kb = r2 / 32;
        const int lane = r2 % 32;
        const int gid = lane >> 2, qid = lane & 3;
        const int o = nb * 8 + gid;
        const int c = kb * 16 + qid * 2;
        uint2 v;
        v.x = pack_h2(w_conv[((size_t)o * CC + c) * 9 + k],
                      w_conv[((size_t)o * CC + c + 1) * 9 + k]);
        v.y = pack_h2(w_conv[((size_t)o * CC + c + 8) * 9 + k],
                      w_conv[((size_t)o * CC + c + 9) * 9 + k]);
        g_Bpkh[u] = v;
    } else if (u < NWCONV + NWOFF) {
        const int w = u - NWCONV;
        const int k  = w / 2048;
        const int r  = w % 2048;
        const int cg = r / 512;
        const int r2 = r % 512;
        const int kb = r2 / 128;
        const int r3 = r2 % 128;
        const int nt = r3 / 32;
        const int lane = r3 % 32;
        const int gid = lane >> 2, qid = lane & 3;
        const int o = nt * 8 + gid;
        const int c = cg * 64 + kb * 16 + qid * 2;
        uint2 v = make_uint2(0u, 0u);
        if (o < 27) {
            v.x = pack_h2(w_off[((size_t)o * CC + c) * 9 + k],
                          w_off[((size_t)o * CC + c + 1) * 9 + k]);
            v.y = pack_h2(w_off[((size_t)o * CC + c + 8) * 9 + k],
                          w_off[((size_t)o * CC + c + 9) * 9 + k]);
        }
        g_Woffh[w] = v;
    }
}

// =============================================================================
// offset_mma: om[b][27][h][x] = conv3x3(x, w_off) + b_off via fp16 MMA
// =============================================================================
#define OC_RS 72
#define OC_ASM_BYTES (((3 * 98 * OC_RS * 2) + 15) & ~15)
#define OC_SMEM (OC_ASM_BYTES + 9 * 512 * 8)

__global__ __launch_bounds__(192) void offset_mma_kernel(const float* __restrict__ b_off)
{
    extern __shared__ __align__(16) char osm[];
    __half* Asm = (__half*)osm;                       // [3][98][OC_RS]
    uint2*  Bsm = (uint2*)(osm + OC_ASM_BYTES);       // [9][512]

    const int tid = threadIdx.x;
    const int warp = tid >> 5, lane = tid & 31;
    const int gid = lane >> 2, qid = lane & 3;
    const int h = blockIdx.x, b = blockIdx.y;

    float acc[4][4];
#pragma unroll
    for (int nt = 0; nt < 4; nt++)
#pragma unroll
        for (int e = 0; e < 4; e++) acc[nt][e] = 0.f;

    for (int cg = 0; cg < 4; cg++) {
        __syncthreads();
        for (int t = tid; t < 9 * 512; t += 192)
            Bsm[t] = g_Woffh[(size_t)((t >> 9) * 4 + cg) * 512 + (t & 511)];
        for (int t = tid; t < 3 * 98 * 8; t += 192) {
            const int ky = t / (98 * 8);
            const int rr = t % (98 * 8);
            const int i = rr >> 3, j = rr & 7;
            const int hh = h + ky - 1;
            const int xx = i - 1;
            uint4 v = make_uint4(0u, 0u, 0u, 0u);
            if (hh >= 0 && hh < HH && xx >= 0 && xx < WW)
                v = *(const uint4*)(g_Axh + ((size_t)b * HWP + hh * WW + xx) * CC
                                    + cg * 64 + j * 8);
            *(uint4*)&Asm[(ky * 98 + i) * OC_RS + j * 8] = v;
        }
        __syncthreads();

        for (int k = 0; k < 9; k++) {
            const int ky = k / 3, kx = k % 3;
            const __half* Ab = Asm + (size_t)ky * 98 * OC_RS;
            const uint2* Bk = Bsm + k * 512;
            const int row = warp * 16 + gid + kx;
#pragma unroll
            for (int kb = 0; kb < 4; kb++) {
                const int c0 = kb * 16 + qid * 2;
                uint32_t a[4];
                a[0] = *(const uint32_t*)&Ab[row * OC_RS + c0];
                a[1] = *(const uint32_t*)&Ab[(row + 8) * OC_RS + c0];
                a[2] = *(const uint32_t*)&Ab[row * OC_RS + c0 + 8];
                a[3] = *(const uint32_t*)&Ab[(row + 8) * OC_RS + c0 + 8];
#pragma unroll
                for (int nt = 0; nt < 4; nt++) {
                    const uint2 bv = Bk[(kb * 4 + nt) * 32 + lane];
                    uint32_t bf[2] = { bv.x, bv.y };
                    mma_f16(acc[nt], a, bf);
                }
            }
        }
    }

#pragma unroll
    for (int nt = 0; nt < 4; nt++) {
#pragma unroll
        for (int e = 0; e < 4; e++) {
            const int o = nt * 8 + qid * 2 + (e & 1);
            const int xx = warp * 16 + gid + ((e >= 2) ? 8 : 0);
            if (o < 27)
                g_om[((size_t)b * 27 + o) * HWP + h * WW + xx] = acc[nt][e] + b_off[o];
        }
    }
}

// =============================================================================
// gemm: Z[z][p][o] = sum_c A[b][p][c]*B[k][o][c]; fp16 in, fp32 acc, fp16 out
// BM=128 BN=128 BK=64, 128 thr (2x2 warps, 64x64), 3-stage cp.async pipeline,
// register double-buffered fragments (LDS for ks+1 overlaps MMAs of ks)
// =============================================================================
#define GEMM_SMEM 98304

__global__ __launch_bounds__(128, 2) void gemm_f16_kernel()
{
    extern __shared__ __align__(16) char gsm[];
    const uint32_t u0 = smem_u32(gsm);

    const int tid  = threadIdx.x;
    const int warp = tid >> 5;
    const int lane = tid & 31;
    const int gid  = lane >> 2;
    const int qid  = lane & 3;
    const int wy   = warp >> 1;
    const int wx   = warp & 1;

    const int pb0 = blockIdx.x * 8;
    const int nb0 = blockIdx.y * 16;
    const int z   = blockIdx.z;
    const int b   = z / K9, k = z % K9;

    const uint4* Abase = g_Apkh + (size_t)b * 576 * 16 * 32;
    const uint2* Bbase = g_Bpkh + (size_t)k * 32 * 16 * 32;

    const int akb = (tid >> 5) & 3;
    const int alane = tid & 31;
    const int bkb = (tid >> 4) & 3;
    const int bpair = tid & 15;
    const int bnbh = tid >> 6;

    auto load_stage = [&](int s, int kc) {
        const uint32_t sa = u0 + s * 32768;
        const uint32_t sb = sa + 16384;
#pragma unroll
        for (int it = 0; it < 8; it++) {
            cp_async16(sa + (uint32_t)(it * 128 + tid) * 16,
                       Abase + ((size_t)(pb0 + it) * 16 + kc * 4 + akb) * 32 + alane);
            cp_async16(sb + (uint32_t)(it * 128 + tid) * 16,
                       Bbase + ((size_t)(nb0 + it * 2 + bnbh) * 16 + kc * 4 + bkb) * 32
                             + bpair * 2);
        }
        CP_COMMIT();
    };

    float acc[4][8][4];
#pragma unroll
    for (int mt = 0; mt < 4; mt++)
#pragma unroll
        for (int nt = 0; nt < 8; nt++)
#pragma unroll
            for (int e = 0; e < 4; e++) acc[mt][nt][e] = 0.f;

    uint32_t afr[2][4][4], bfr[2][8][2];

    load_stage(0, 0);
    load_stage(1, 1);

#pragma unroll 1
    for (int kc = 0; kc < 4; kc++) {
        if (kc < 3) { CP_WAIT1(); } else { CP_WAIT0(); }
        __syncthreads();

        char* ca = gsm + (kc % 3) * 32768;
        char* cb = ca + 16384;

        // prefetch fragments for ks=0 of this stage
#pragma unroll
        for (int mt = 0; mt < 4; mt++) {
            const uint4 v = *(const uint4*)(ca + (((wy * 4 + mt) * 4) * 32 + lane) * 16);
            afr[0][mt][0] = v.x; afr[0][mt][1] = v.y;
            afr[0][mt][2] = v.z; afr[0][mt][3] = v.w;
        }
#pragma unroll
        for (int nt = 0; nt < 8; nt++) {
            const uint2 v = *(const uint2*)(cb + (((wx * 8 + nt) * 4) * 32 + lane) * 8);
            bfr[0][nt][0] = v.x; bfr[0][nt][1] = v.y;
        }

        if (kc < 2) load_stage((kc + 2) % 3, kc + 2);

#pragma unroll
        for (int ks = 0; ks < 4; ks++) {
            const int cur = ks & 1;
            if (ks < 3) {
                const int nxt = cur ^ 1;
#pragma unroll
                for (int mt = 0; mt < 4; mt++) {
                    const uint4 v = *(const uint4*)(ca
                        + (((wy * 4 + mt) * 4 + ks + 1) * 32 + lane) * 16);
                    afr[nxt][mt][0] = v.x; afr[nxt][mt][1] = v.y;
                    afr[nxt][mt][2] = v.z; afr[nxt][mt][3] = v.w;
                }
#pragma unroll
                for (int nt = 0; nt < 8; nt++) {
                    const uint2 v = *(const uint2*)(cb
                        + (((wx * 8 + nt) * 4 + ks + 1) * 32 + lane) * 8);
                    bfr[nxt][nt][0] = v.x; bfr[nxt][nt][1] = v.y;
                }
            }
#pragma unroll
            for (int mt = 0; mt < 4; mt++)
#pragma unroll
                for (int nt = 0; nt < 8; nt++)
                    mma_f16(acc[mt][nt], afr[cur][mt], bfr[cur][nt]);
        }
    }

    // epilogue: stage fp16 tile in smem (row pad 132 half2), then coalesced store
    __syncthreads();
    __half2* st = (__half2*)gsm;
#pragma unroll
    for (int mt = 0; mt < 4; mt++) {
        const int r0 = wy * 64 + mt * 16 + gid;
#pragma unroll
        for (int nt = 0; nt < 8; nt++) {
            const int n2 = wx * 32 + nt * 4 + qid;
            st[r0 * 132 + n2]       = __floats2half2_rn(acc[mt][nt][0], acc[mt][nt][1]);
            st[(r0 + 8) * 132 + n2] = __floats2half2_rn(acc[mt][nt][2], acc[mt][nt][3]);
        }
    }
    __syncthreads();

    uint4* Z4 = (uint4*)g_Zh;
#pragma unroll
    for (int it = 0; it < 16; it++) {
        const int idx = it * 128 + tid;
        const int row = idx >> 4;
        const int ch  = idx & 15;
        const uint4 v = *(const uint4*)(gsm + row * 528 + ch * 16);
        Z4[((size_t)z * HWP + pb0 * 16 + row) * 32 + nb0 + ch] = v;
    }
}

// =============================================================================
// combine (prep fused): sampling meta from g_om inline, gather Z fp16,
// BN+ReLU+residual.
// =============================================================================
__global__ __launch_bounds__(256) void combine_kernel(
    const float* __restrict__ x, const float* __restrict__ b_conv,
    const float* __restrict__ gamma, const float* __restrict__ beta,
    const float* __restrict__ run_mean, const float* __restrict__ run_var,
    float* __restrict__ out)
{
    __shared__ int   sI[32][36];
    __shared__ float sWt[32][36];
    __shared__ float sA[256], sB[256];
    __shared__ float trans[256 * 33];

    const int b  = blockIdx.y;
    const int p0 = blockIdx.x * 32;
    const int tid = threadIdx.x;

    {
        const int o = tid;
        const float inv = rsqrtf(run_var[o] + EPSBN);
        const float a = inv * gamma[o];
        sA[o] = a;
        sB[o] = (b_conv[o] - run_mean[o]) * a + beta[o];
    }

    const float* omb = g_om + (size_t)b * 27 * HWP;
    for (int i = tid; i < 32 * 9; i += 256) {
        const int px = i & 31;
        const int k  = i >> 5;
        const int p  = p0 + px;

        const float dy = omb[(2 * k) * HWP + p];
        const float dx = omb[(2 * k + 1) * HWP + p];
        const float mv = omb[(18 + k) * HWP + p];
        const float m  = 1.f / (1.f + expf(-mv));

        const int h = p / WW, w = p - h * WW;
        const float py = (float)h + (float)(k / 3 - 1) + dy;
        const float px_ = (float)w + (float)(k % 3 - 1) + dx;
        const float y0f = floorf(py), x0f = floorf(px_);
        const float ly = py - y0f, lx = px_ - x0f;
        const int y0 = (int)y0f, x0 = (int)x0f;
        const int y1 = y0 + 1,   x1 = x0 + 1;

        const bool vy0 = (y0 >= 0) & (y0 < HH);
        const bool vy1 = (y1 >= 0) & (y1 < HH);
        const bool vx0 = (x0 >= 0) & (x0 < WW);
        const bool vx1 = (x1 >= 0) & (x1 < WW);
        const int y0c = min(max(y0, 0), HH - 1), y1c = min(max(y1, 0), HH - 1);
        const int x0c = min(max(x0, 0), WW - 1), x1c = min(max(x1, 0), WW - 1);

        int4 idx;
        idx.x = y0c * WW + x0c;
        idx.y = y0c * WW + x1c;
        idx.z = y1c * WW + x0c;
        idx.w = y1c * WW + x1c;
        float4 wt;
        wt.x = (1.f - ly) * (1.f - lx) * m * ((vy0 & vx0) ? 1.f : 0.f);
        wt.y = (1.f - ly) * lx         * m * ((vy0 & vx1) ? 1.f : 0.f);
        wt.z = ly * (1.f - lx)         * m * ((vy1 & vx0) ? 1.f : 0.f);
        wt.w = ly * lx                 * m * ((vy1 & vx1) ? 1.f : 0.f);

        *(int4*)&sI[px][k * 4]    = idx;
        *(float4*)&sWt[px][k * 4] = wt;
    }
    __syncthreads();

    const int og  = tid & 7;
    const int pxl = tid >> 3;

    float acc[4][8];
#pragma unroll
    for (int t = 0; t < 4; t++)
#pragma unroll
        for (int e = 0; e < 8; e++) acc[t][e] = 0.f;

    for (int k = 0; k < K9; k++) {
        const uint4* Zk = reinterpret_cast<const uint4*>(g_Zh)
                        + ((size_t)(b * K9 + k)) * HWP * 32;
#pragma unroll
        for (int j = 0; j < 4; j++) {
            const int   idx = sI[pxl][k * 4 + j];
            const float wj  = sWt[pxl][k * 4 + j];
            const uint4* src = Zk + (size_t)idx * 32 + og;
#pragma unroll
            for (int t = 0; t < 4; t++) {
                const uint4 u = src[t * 8];
                const float2 f0 = __half22float2(*reinterpret_cast<const __half2*>(&u.x));
                const float2 f1 = __half22float2(*reinterpret_cast<const __half2*>(&u.y));
                const float2 f2 = __half22float2(*reinterpret_cast<const __half2*>(&u.z));
                const float2 f3 = __half22float2(*reinterpret_cast<const __half2*>(&u.w));
                acc[t][0] += wj * f0.x; acc[t][1] += wj * f0.y;
                acc[t][2] += wj * f1.x; acc[t][3] += wj * f1.y;
                acc[t][4] += wj * f2.x; acc[t][5] += wj * f2.y;
                acc[t][6] += wj * f3.x; acc[t][7] += wj * f3.y;
            }
        }
    }

#pragma unroll
    for (int t = 0; t < 4; t++)
#pragma unroll
        for (int e = 0; e < 8; e++) {
            const int o = t * 64 + og * 8 + e;
            trans[o * 33 + pxl] = acc[t][e];
        }
    __syncthreads();

    const float* xb = x + ((size_t)b * CC) * HWP;
    float* ob = out + ((size_t)b * CC) * HWP;
    for (int pass = 0; pass < 32; pass++) {
        const int o   = (tid >> 5) + pass * 8;
        const int pxi = tid & 31;
        float v = trans[o * 33 + pxi];
        v = fmaxf(v * sA[o] + sB[o], 0.f);
        const size_t gi = (size_t)o * HWP + p0 + pxi;
        ob[gi] = xb[gi] + v;
    }
}

// =============================================================================
extern "C" void kernel_launch(void* const* d_in, const int* in_sizes, int n_in,
                              void* d_out, int out_size)
{
    const float* x        = (const float*)d_in[0];
    const float* w_off    = (const float*)d_in[1];
    const float* b_off    = (const float*)d_in[2];
    const float* w_conv   = (const float*)d_in[3];
    const float* b_conv   = (const float*)d_in[4];
    const float* gamma    = (const float*)d_in[5];
    const float* beta     = (const float*)d_in[6];
    const float* run_mean = (const float*)d_in[7];
    const float* run_var  = (const float*)d_in[8];
    float* out = (float*)d_out;

    cudaFuncSetAttribute(gemm_f16_kernel,
                         cudaFuncAttributeMaxDynamicSharedMemorySize, GEMM_SMEM);
    cudaFuncSetAttribute(offset_mma_kernel,
                         cudaFuncAttributeMaxDynamicSharedMemorySize, OC_SMEM);

    pack_a_fused_kernel<<<dim3(576, BB), 256>>>(x);
    pack_weights_kernel<<<(NWCONV + NWOFF + 255) / 256, 256>>>(w_conv, w_off);
    offset_mma_kernel<<<dim3(HH, BB), 192, OC_SMEM>>>(b_off);
    gemm_f16_kernel<<<dim3(HWP / 128, CC / 128, BB * K9), 128, GEMM_SMEM>>>();
    combine_kernel<<<dim3(HWP / 32, BB), 256>>>(x, b_conv, gamma, beta,
                                                run_mean, run_var, out);
}